// round 5
// baseline (speedup 1.0000x reference)
#include <cuda_runtime.h>
#include <math.h>
#include <stdint.h>

#define B_  8
#define LP_ 1000
#define NC_ 64
#define D_  128
#define E_  320
#define NTILE_ 100
#define ITILE_ 10
typedef long long ll;

// ---------------- scratch (device globals) ----------------------------------
__device__ __align__(16) uint2 g_Qhl[B_*LP_*D_];
__device__ __align__(16) uint2 g_Khl[B_*LP_*D_];
__device__ __align__(16) uint2 g_Vhl[B_*LP_*D_];
__device__ __align__(16) uint2 g_Chl[B_*NC_*D_];
__device__ __align__(16) uint2 g_Wqhl[E_*D_];
__device__ __align__(16) uint2 g_wkhl[D_*D_];
__device__ __align__(16) uint2 g_wvhl[D_*D_];
__device__ __align__(16) uint2 g_wohl[D_*D_];
__device__ __align__(16) uint2 g_jphl[D_*D_];
__device__ __align__(16) uint2 g_jchl[D_*D_];
__device__ __align__(16) uint2 g_wqhl0[D_*D_];
__device__ __align__(16) float g_AV0[B_*LP_*D_];
__device__ __align__(16) float g_AV1[B_*LP_*D_];
__device__ __align__(16) float g_pf [B_*LP_*D_];
__device__ __align__(16) float g_P  [B_*LP_*D_];
__device__ __align__(16) float g_S  [B_*LP_*LP_];
__device__ __align__(16) float g_A  [B_*LP_*NC_];
__device__ __align__(16) float g_bq [D_];
__device__ __align__(16) float g_Apart[B_*16];
__device__ __align__(16) float g_part[B_*NTILE_*D_];
__device__ __align__(16) float g_cp [B_*D_];
__device__ __align__(16) float g_h1 [B_*1024];
__device__ __align__(16) float g_h2 [B_*1024];
__device__ __align__(16) float g_h3 [B_*256];

// ---------------- tf32 helpers ----------------------------------------------
__device__ __forceinline__ uint32_t f2tf32(float x) {
    uint32_t r;
    asm("cvt.rna.tf32.f32 %0, %1;" : "=r"(r) : "f"(x));
    return r;
}
__device__ __forceinline__ uint32_t f2lo(float x, uint32_t h) {
    return f2tf32(x - __uint_as_float(h));
}
__device__ __forceinline__ void mma_tf32(float* d, const uint32_t* a, const uint32_t* b) {
    asm volatile(
        "mma.sync.aligned.m16n8k8.row.col.f32.tf32.tf32.f32 "
        "{%0,%1,%2,%3}, {%4,%5,%6,%7}, {%8,%9}, {%0,%1,%2,%3};\n"
        : "+f"(d[0]), "+f"(d[1]), "+f"(d[2]), "+f"(d[3])
        : "r"(a[0]), "r"(a[1]), "r"(a[2]), "r"(a[3]), "r"(b[0]), "r"(b[1]));
}
__device__ __forceinline__ void cvt_store4(uint2* base, int idx, float4 v) {
    uint32_t h0 = f2tf32(v.x), h1 = f2tf32(v.y), h2 = f2tf32(v.z), h3 = f2tf32(v.w);
    *(uint4*)(base + idx)     = make_uint4(h0, f2lo(v.x, h0), h1, f2lo(v.y, h1));
    *(uint4*)(base + idx + 2) = make_uint4(h2, f2lo(v.z, h2), h3, f2lo(v.w, h3));
}
__device__ __forceinline__ void cvt_store2(uint2* base, int idx, float2 v) {
    uint32_t h0 = f2tf32(v.x), h1 = f2tf32(v.y);
    *(uint4*)(base + idx) = make_uint4(h0, f2lo(v.x, h0), h1, f2lo(v.y, h1));
}

// ---------------- unified big GEMM body: 64(M) x 128(N) tile, BK=8 ----------
// AMODE: 0=A fp32, 1=A fp32+relu, 2=A hi/lo uint2, 3=A fp32 dual-add
// B always pre-converted uint2 (hi,lo). EPI: 0=fp32 out, 1=hi/lo uint2 out.
// smem: A [m][k] pitch 12 (uint2); trans-B [n][k] pitch 12; non-trans [k][n] 132.
template<int AMODE, bool TRANS_B, int EPI>
__device__ __forceinline__ void gemm_body(
    const float* __restrict__ Af, const float* __restrict__ Af2,
    const uint2* __restrict__ Ah, const uint2* __restrict__ Bh,
    const float* __restrict__ bias, float* __restrict__ Cf, uint2* __restrict__ Ch,
    int M, int N, int K, int lda, float alpha, int m0, int n0,
    uint2* As, uint2* Bs)
{
    constexpr int ASN = 64 * 12;
    constexpr int BSN = TRANS_B ? 128 * 12 : 8 * 132;

    int t = threadIdx.x, warp = t >> 5, lane = t & 31;
    int g = lane >> 2, l3 = lane & 3;
    int wm = (warp & 1) * 32, wn = (warp >> 1) * 32;

    float acc[2][4][4] = {};

    int ar  = t >> 2, ak  = (t & 3) * 2;   // A: row 0..63, k-pair
    int btr = t >> 1, btk = (t & 1) * 4;   // trans-B: row 0..127, k-quad
    int bk  = t >> 5, bnq = (t & 31) * 4;  // non-trans-B: k 0..7, n-quad

    int kt = K >> 3;                       // K always multiple of 8
    float2 ra; uint4 ua, ub0, ub1;

    auto loadA = [&](int k0) {
        int gm = m0 + ar, gk = k0 + ak;
        if (AMODE == 2) {
            ua = make_uint4(0u, 0u, 0u, 0u);
            if (gm < M) ua = *(const uint4*)(Ah + (ll)gm * lda + gk);
        } else {
            ra = make_float2(0.f, 0.f);
            if (gm < M) {
                ra = *(const float2*)(Af + (ll)gm * lda + gk);
                if (AMODE == 3) {
                    float2 r2 = *(const float2*)(Af2 + (ll)gm * lda + gk);
                    ra.x += r2.x; ra.y += r2.y;
                }
                if (AMODE == 1) { ra.x = fmaxf(ra.x, 0.f); ra.y = fmaxf(ra.y, 0.f); }
            }
        }
    };
    auto loadB = [&](int k0) {
        if (TRANS_B) {
            int gn = n0 + btr, gk = k0 + btk;
            ub0 = make_uint4(0u, 0u, 0u, 0u); ub1 = ub0;
            if (gn < N) {
                const uint2* p = Bh + (ll)gn * K + gk;
                ub0 = *(const uint4*)p;
                ub1 = *(const uint4*)(p + 2);
            }
        } else {
            const uint2* p = Bh + (ll)(k0 + bk) * N + bnq;
            ub0 = *(const uint4*)p;
            ub1 = *(const uint4*)(p + 2);
        }
    };
    auto storeA = [&](int s) {
        if (AMODE == 2) *(uint4*)&As[s * ASN + ar * 12 + ak] = ua;
        else            cvt_store2(As + s * ASN, ar * 12 + ak, ra);
    };
    auto storeB = [&](int s) {
        if (TRANS_B) {
            *(uint4*)&Bs[s * BSN + btr * 12 + btk]     = ub0;
            *(uint4*)&Bs[s * BSN + btr * 12 + btk + 2] = ub1;
        } else {
            *(uint4*)&Bs[s * BSN + bk * 132 + bnq]     = ub0;
            *(uint4*)&Bs[s * BSN + bk * 132 + bnq + 2] = ub1;
        }
    };

    loadA(0); loadB(0);
    storeA(0); storeB(0);
    __syncthreads();

    for (int it = 0; it < kt; it++) {
        int s = it & 1;
        if (it + 1 < kt) { loadA((it + 1) << 3); loadB((it + 1) << 3); }

        uint32_t ahi[2][4], alo[2][4];
        #pragma unroll
        for (int mi = 0; mi < 2; mi++) {
            int rr = wm + mi * 16 + g;
            uint2 x0 = As[s * ASN + rr * 12 + l3];
            uint2 x1 = As[s * ASN + (rr + 8) * 12 + l3];
            uint2 x2 = As[s * ASN + rr * 12 + l3 + 4];
            uint2 x3 = As[s * ASN + (rr + 8) * 12 + l3 + 4];
            ahi[mi][0] = x0.x; alo[mi][0] = x0.y;
            ahi[mi][1] = x1.x; alo[mi][1] = x1.y;
            ahi[mi][2] = x2.x; alo[mi][2] = x2.y;
            ahi[mi][3] = x3.x; alo[mi][3] = x3.y;
        }
        uint32_t bhi[4][2], blo[4][2];
        #pragma unroll
        for (int ni = 0; ni < 4; ni++) {
            int cc = wn + ni * 8 + g;
            uint2 y0 = TRANS_B ? Bs[s * BSN + cc * 12 + l3]
                               : Bs[s * BSN + l3 * 132 + cc];
            uint2 y1 = TRANS_B ? Bs[s * BSN + cc * 12 + l3 + 4]
                               : Bs[s * BSN + (l3 + 4) * 132 + cc];
            bhi[ni][0] = y0.x; blo[ni][0] = y0.y;
            bhi[ni][1] = y1.x; blo[ni][1] = y1.y;
        }
        #pragma unroll
        for (int mi = 0; mi < 2; mi++)
            #pragma unroll
            for (int ni = 0; ni < 4; ni++) {
                mma_tf32(acc[mi][ni], ahi[mi], bhi[ni]);
                mma_tf32(acc[mi][ni], ahi[mi], blo[ni]);
                mma_tf32(acc[mi][ni], alo[mi], bhi[ni]);
            }
        if (it + 1 < kt) { storeA(s ^ 1); storeB(s ^ 1); }
        __syncthreads();
    }

    // epilogue: v = (acc + bias) * alpha
    #pragma unroll
    for (int mi = 0; mi < 2; mi++)
        #pragma unroll
        for (int ni = 0; ni < 4; ni++) {
            int r0 = m0 + wm + mi * 16 + g;
            int c0 = n0 + wn + ni * 8 + 2 * l3;
            if (c0 >= N) continue;
            float b0 = 0.f, b1 = 0.f;
            if (bias) { b0 = bias[c0]; b1 = bias[c0 + 1]; }
            float v00 = (acc[mi][ni][0] + b0) * alpha;
            float v01 = (acc[mi][ni][1] + b1) * alpha;
            float v10 = (acc[mi][ni][2] + b0) * alpha;
            float v11 = (acc[mi][ni][3] + b1) * alpha;
            if (EPI == 0) {
                if (r0 < M)     *(float2*)(Cf + (ll)r0 * N + c0)       = make_float2(v00, v01);
                if (r0 + 8 < M) *(float2*)(Cf + (ll)(r0 + 8) * N + c0) = make_float2(v10, v11);
            } else {
                if (r0 < M) {
                    uint32_t h0 = f2tf32(v00), h1 = f2tf32(v01);
                    *(uint4*)(Ch + (ll)r0 * N + c0) =
                        make_uint4(h0, f2lo(v00, h0), h1, f2lo(v01, h1));
                }
                if (r0 + 8 < M) {
                    uint32_t h0 = f2tf32(v10), h1 = f2tf32(v11);
                    *(uint4*)(Ch + (ll)(r0 + 8) * N + c0) =
                        make_uint4(h0, f2lo(v10, h0), h1, f2lo(v11, h1));
                }
            }
        }
}

// ---------------- wrappers ----------------------------------------------------
// prep: convert 6 weight matrices fp32 -> (hi,lo)
__global__ void prep6_kernel(const float* w0, const float* w1, const float* w2,
                             const float* w3, const float* w4, const float* w5,
                             uint2* d0, uint2* d1, uint2* d2,
                             uint2* d3, uint2* d4, uint2* d5)
{
    int i = blockIdx.x * 256 + threadIdx.x;   // 0..16383
    const float* s; uint2* d;
    switch (blockIdx.y) {
        case 0: s = w0; d = d0; break;
        case 1: s = w1; d = d1; break;
        case 2: s = w2; d = d2; break;
        case 3: s = w3; d = d3; break;
        case 4: s = w4; d = d4; break;
        default: s = w5; d = d5; break;
    }
    float v = s[i];
    uint32_t h = f2tf32(v);
    d[i] = make_uint2(h, f2lo(v, h));
}

// Wq' = emb_w @ wq_w  -> hi/lo
__global__ void __launch_bounds__(256, 2)
gemm_wqp(const float* __restrict__ emb_w, const uint2* __restrict__ wq_hl,
         uint2* __restrict__ Wq_hl)
{
    __shared__ __align__(16) uint2 As[2 * 64 * 12];
    __shared__ __align__(16) uint2 Bs[2 * 8 * 132];
    gemm_body<0, false, 1>(emb_w, nullptr, nullptr, wq_hl, nullptr, nullptr, Wq_hl,
        E_, D_, D_, D_, 1.f, blockIdx.y * 64, 0, As, Bs);
}

__global__ void __launch_bounds__(256, 2)
gemm_qkv(const float* __restrict__ in_pe, const uint2* __restrict__ Wq_hl,
         const float* __restrict__ bq, uint2* __restrict__ Qhl,
         const float* __restrict__ in_pfx,
         const uint2* __restrict__ wk_hl, const float* __restrict__ wk_b,
         uint2* __restrict__ Khl,
         const uint2* __restrict__ wv_hl, const float* __restrict__ wv_b,
         uint2* __restrict__ Vhl, float inv_sqrt_d)
{
    __shared__ __align__(16) uint2 As[2 * 64 * 12];
    __shared__ __align__(16) uint2 Bs[2 * 8 * 132];
    int m0 = blockIdx.y * 64;
    if (blockIdx.z == 0)
        gemm_body<0, false, 1>(in_pe, nullptr, nullptr, Wq_hl, bq, nullptr, Qhl,
            B_*LP_, D_, E_, E_, inv_sqrt_d, m0, 0, As, Bs);
    else if (blockIdx.z == 1)
        gemm_body<0, false, 1>(in_pfx, nullptr, nullptr, wk_hl, wk_b, nullptr, Khl,
            B_*LP_, D_, D_, D_, 1.f, m0, 0, As, Bs);
    else
        gemm_body<0, false, 1>(in_pfx, nullptr, nullptr, wv_hl, wv_b, nullptr, Vhl,
            B_*LP_, D_, D_, D_, 1.f, m0, 0, As, Bs);
}

// S = Qs @ K^T  (scale already folded into Q)
__global__ void __launch_bounds__(256, 2)
gemm_qk(const uint2* __restrict__ Qhl, const uint2* __restrict__ Khl,
        float* __restrict__ S)
{
    __shared__ __align__(16) uint2 As[2 * 64 * 12];
    __shared__ __align__(16) uint2 Bs[2 * 128 * 12];
    int b = blockIdx.z;
    gemm_body<2, true, 0>(nullptr, nullptr,
        Qhl + (ll)b * LP_ * D_, Khl + (ll)b * LP_ * D_, nullptr,
        S + (ll)b * LP_ * LP_, nullptr,
        LP_, LP_, D_, D_, 1.f, blockIdx.y * 64, blockIdx.x * 128, As, Bs);
}

// AV split-K=2
__global__ void __launch_bounds__(256, 2)
gemm_av(const float* __restrict__ S, const uint2* __restrict__ Vhl,
        float* __restrict__ AV0, float* __restrict__ AV1)
{
    __shared__ __align__(16) uint2 As[2 * 64 * 12];
    __shared__ __align__(16) uint2 Bs[2 * 8 * 132];
    int b = blockIdx.z >> 1, half = blockIdx.z & 1;
    int kOff = half * 512, kLen = half ? 488 : 512;
    float* out = half ? AV1 : AV0;
    gemm_body<0, false, 0>(
        S + (ll)b * LP_ * LP_ + kOff, nullptr, nullptr,
        Vhl + ((ll)b * LP_ + kOff) * D_, nullptr,
        out + (ll)b * LP_ * D_, nullptr,
        LP_, D_, kLen, LP_, 1.f, blockIdx.y * 64, 0, As, Bs);
}

// pf = (AV0 + AV1) @ wo + wo_b
__global__ void __launch_bounds__(256, 2)
gemm_wo(const float* __restrict__ AV0, const float* __restrict__ AV1,
        const uint2* __restrict__ wo_hl, const float* __restrict__ wo_b,
        float* __restrict__ pf)
{
    __shared__ __align__(16) uint2 As[2 * 64 * 12];
    __shared__ __align__(16) uint2 Bs[2 * 8 * 132];
    gemm_body<3, false, 0>(AV0, AV1, nullptr, wo_hl, wo_b, pf, nullptr,
        B_*LP_, D_, D_, D_, 1.f, blockIdx.y * 64, 0, As, Bs);
}

// P = relu(pf)@jp + b (fp32) ; Chl = relu(cf)@jc + b (hi/lo)
__global__ void __launch_bounds__(256, 2)
gemm_pc(const float* __restrict__ pf, const uint2* __restrict__ jp_hl,
        const float* __restrict__ jp_b, float* __restrict__ P,
        const float* __restrict__ cf, const uint2* __restrict__ jc_hl,
        const float* __restrict__ jc_b, uint2* __restrict__ Chl)
{
    if (blockIdx.z == 1 && blockIdx.y >= 8) return;
    __shared__ __align__(16) uint2 As[2 * 64 * 12];
    __shared__ __align__(16) uint2 Bs[2 * 8 * 132];
    int m0 = blockIdx.y * 64;
    if (blockIdx.z == 0)
        gemm_body<1, false, 0>(pf, nullptr, nullptr, jp_hl, jp_b, P, nullptr,
            B_*LP_, D_, D_, D_, 1.f, m0, 0, As, Bs);
    else
        gemm_body<1, false, 1>(cf, nullptr, nullptr, jc_hl, jc_b, nullptr, Chl,
            B_*NC_, D_, D_, D_, 1.f, m0, 0, As, Bs);
}

// ---------------- A-logits: 64x64 GEMM + sigmoid + partial sums --------------
__global__ void __launch_bounds__(256, 2)
alogits_kernel(const float* __restrict__ Pm, const uint2* __restrict__ Chl,
               float* __restrict__ Aout, float* __restrict__ Apart)
{
    __shared__ __align__(16) uint2 As[2][64 * 20];
    __shared__ __align__(16) uint2 Bs[2][64 * 20];
    __shared__ float red[256];

    int b = blockIdx.y, mt = blockIdx.x;
    const float* A = Pm + (ll)b * LP_ * D_;
    const uint2* Bmh = Chl + (ll)b * NC_ * D_;
    float* C = Aout + (ll)b * LP_ * NC_;
    int m0 = mt * 64;
    int t = threadIdx.x, warp = t >> 5, lane = t & 31;
    int g = lane >> 2, l3 = lane & 3;
    int wm = (warp & 1) * 32, wn = (warp >> 1) * 16;

    float acc[2][2][4] = {};
    int arow = t >> 2, akq = (t & 3) * 4;
    const int K = D_, M = LP_;
    int kt = K >> 4;
    float4 ra; uint4 ub0, ub1;
    {
        int gm = m0 + arow;
        ra = make_float4(0.f, 0.f, 0.f, 0.f);
        if (gm < M) ra = *(const float4*)(A + (ll)gm * K + akq);
        ub0 = *(const uint4*)(Bmh + (ll)arow * K + akq);
        ub1 = *(const uint4*)(Bmh + (ll)arow * K + akq + 2);
        cvt_store4(As[0], arow * 20 + akq, ra);
        *(uint4*)&Bs[0][arow * 20 + akq]     = ub0;
        *(uint4*)&Bs[0][arow * 20 + akq + 2] = ub1;
    }
    __syncthreads();
    for (int it = 0; it < kt; it++) {
        int s = it & 1;
        if (it + 1 < kt) {
            int k0 = (it + 1) << 4;
            int gm = m0 + arow;
            ra = make_float4(0.f, 0.f, 0.f, 0.f);
            if (gm < M) ra = *(const float4*)(A + (ll)gm * K + k0 + akq);
            ub0 = *(const uint4*)(Bmh + (ll)arow * K + k0 + akq);
            ub1 = *(const uint4*)(Bmh + (ll)arow * K + k0 + akq + 2);
        }
        #pragma unroll
        for (int ks = 0; ks < 2; ks++) {
            int kb = ks * 8 + l3;
            uint32_t ahi[2][4], alo[2][4];
            #pragma unroll
            for (int mi = 0; mi < 2; mi++) {
                int rr = wm + mi * 16 + g;
                uint2 x0 = As[s][rr * 20 + kb];
                uint2 x1 = As[s][(rr + 8) * 20 + kb];
                uint2 x2 = As[s][rr * 20 + kb + 4];
                uint2 x3 = As[s][(rr + 8) * 20 + kb + 4];
                ahi[mi][0] = x0.x; alo[mi][0] = x0.y;
                ahi[mi][1] = x1.x; alo[mi][1] = x1.y;
                ahi[mi][2] = x2.x; alo[mi][2] = x2.y;
                ahi[mi][3] = x3.x; alo[mi][3] = x3.y;
            }
            uint32_t bhi[2][2], blo[2][2];
            #pragma unroll
            for (int ni = 0; ni < 2; ni++) {
                int cc = wn + ni * 8 + g;
                uint2 y0 = Bs[s][cc * 20 + kb];
                uint2 y1 = Bs[s][cc * 20 + kb + 4];
                bhi[ni][0] = y0.x; blo[ni][0] = y0.y;
                bhi[ni][1] = y1.x; blo[ni][1] = y1.y;
            }
            #pragma unroll
            for (int mi = 0; mi < 2; mi++)
                #pragma unroll
                for (int ni = 0; ni < 2; ni++) {
                    mma_tf32(acc[mi][ni], ahi[mi], bhi[ni]);
                    mma_tf32(acc[mi][ni], ahi[mi], blo[ni]);
                    mma_tf32(acc[mi][ni], alo[mi], bhi[ni]);
                }
        }
        if (it + 1 < kt) {
            cvt_store4(As[s ^ 1], arow * 20 + akq, ra);
            *(uint4*)&Bs[s ^ 1][arow * 20 + akq]     = ub0;
            *(uint4*)&Bs[s ^ 1][arow * 20 + akq + 2] = ub1;
        }
        __syncthreads();
    }

    float tsum = 0.f;
    #pragma unroll
    for (int mi = 0; mi < 2; mi++)
        #pragma unroll
        for (int ni = 0; ni < 2; ni++) {
            int r0 = m0 + wm + mi * 16 + g;
            int c0 = wn + ni * 8 + 2 * l3;
            if (r0 < M) {
                float v0 = 1.f / (1.f + __expf(-acc[mi][ni][0]));
                float v1 = 1.f / (1.f + __expf(-acc[mi][ni][1]));
                *(float2*)(C + (ll)r0 * NC_ + c0) = make_float2(v0, v1);
                tsum += v0 + v1;
            }
            if (r0 + 8 < M) {
                float v0 = 1.f / (1.f + __expf(-acc[mi][ni][2]));
                float v1 = 1.f / (1.f + __expf(-acc[mi][ni][3]));
                *(float2*)(C + (ll)(r0 + 8) * NC_ + c0) = make_float2(v0, v1);
                tsum += v0 + v1;
            }
        }
    red[t] = tsum; __syncthreads();
    for (int s2 = 128; s2 > 0; s2 >>= 1) {
        if (t < s2) red[t] += red[t + s2];
        __syncthreads();
    }
    if (t == 0) Apart[b * 16 + mt] = red[0];
}

// ---------------- bq' = emb_b @ wq_w + wq_b ---------------------------------
__global__ void fuse_bq_kernel(const float* __restrict__ emb_b,
                               const float* __restrict__ wq_w,
                               const float* __restrict__ wq_b,
                               float* __restrict__ bq)
{
    int n = threadIdx.x;
    float s = wq_b[n];
    for (int k = 0; k < D_; k++) s = fmaf(emb_b[k], wq_w[k * D_ + n], s);
    bq[n] = s;
}

// ---------------- row softmax -------------------------------------------------
__global__ void softmax_kernel(float* __restrict__ S)
{
    ll row = blockIdx.x;
    float* p = S + row * LP_;
    int t = threadIdx.x;  // 256
    __shared__ float red[256];
    float v[4];
    float mx = -1e30f;
    #pragma unroll
    for (int e = 0; e < 4; e++) {
        int i = t + e * 256;
        v[e] = (i < LP_) ? p[i] : -1e30f;
        mx = fmaxf(mx, v[e]);
    }
    red[t] = mx; __syncthreads();
    for (int s = 128; s > 0; s >>= 1) {
        if (t < s) red[t] = fmaxf(red[t], red[t + s]);
        __syncthreads();
    }
    mx = red[0];
    __syncthreads();
    float sum = 0.f;
    #pragma unroll
    for (int e = 0; e < 4; e++) { v[e] = __expf(v[e] - mx); sum += v[e]; }
    red[t] = sum; __syncthreads();
    for (int s = 128; s > 0; s >>= 1) {
        if (t < s) red[t] += red[t + s];
        __syncthreads();
    }
    float inv = 1.f / red[0];
    #pragma unroll
    for (int e = 0; e < 4; e++) {
        int i = t + e * 256;
        if (i < LP_) p[i] = v[e] * inv;
    }
}

// ---------------- tanh outer-product weighted reduction ---------------------
__global__ void tanh_outer_kernel(const float* __restrict__ pf,
                                  const float* __restrict__ cf,
                                  const float* __restrict__ A,
                                  float* __restrict__ part)
{
    int b = blockIdx.y, tile = blockIdx.x;
    int d = threadIdx.x;  // 128
    __shared__ float cfs[NC_ * D_];
    for (int i = threadIdx.x; i < NC_ * D_; i += 128)
        cfs[i] = cf[(ll)b * NC_ * D_ + i];
    __syncthreads();
    float acc = 0.f;
    int i0 = tile * ITILE_;
    for (int i = i0; i < i0 + ITILE_; i++) {
        float pv = pf[((ll)b * LP_ + i) * D_ + d];
        const float* Ar = A + ((ll)b * LP_ + i) * NC_;
        #pragma unroll 4
        for (int k = 0; k < NC_; k++) {
            float w = Ar[k];
            float x = pv * cfs[k * D_ + d];
            float th;
            asm("tanh.approx.f32 %0, %1;" : "=f"(th) : "f"(x));
            acc = fmaf(th, w, acc);
        }
    }
    part[((ll)b * NTILE_ + tile) * D_ + d] = acc;
}

__global__ void cp_reduce_kernel(const float* __restrict__ part,
                                 const float* __restrict__ Apart,
                                 float* __restrict__ cp)
{
    int b = blockIdx.x;
    int d = threadIdx.x;  // 128
    float as = 0.f;
    #pragma unroll
    for (int j = 0; j < 16; j++) as += Apart[b * 16 + j];
    float s = 0.f;
    for (int t2 = 0; t2 < NTILE_; t2++)
        s += part[((ll)b * NTILE_ + t2) * D_ + d];
    cp[b * D_ + d] = s / as;
}

// ---------------- skinny GEMM (M = 8 rows) -----------------------------------
template<bool RELU_OUT>
__global__ void __launch_bounds__(256)
skinny_gemm(const float* __restrict__ A, const float* __restrict__ W,
            const float* __restrict__ bias, float* __restrict__ C,
            int N, int K)
{
    __shared__ float As[8 * 1024];
    __shared__ float red[8][8][32];
    int t = threadIdx.x;
    for (int i = t; i < 8 * K; i += 256) As[i] = A[i];
    __syncthreads();
    int n = blockIdx.x * 32 + (t & 31);
    int ks = t >> 5;
    int kseg = K >> 3;
    float acc[8] = {};
    if (n < N) {
        for (int k = ks * kseg; k < (ks + 1) * kseg; k++) {
            float w = W[(ll)k * N + n];
            #pragma unroll
            for (int m = 0; m < 8; m++) acc[m] = fmaf(As[m * K + k], w, acc[m]);
        }
    }
    #pragma unroll
    for (int m = 0; m < 8; m++) red[ks][m][t & 31] = acc[m];
    __syncthreads();
    int m = t >> 5, lnn = t & 31;
    int nn = blockIdx.x * 32 + lnn;
    if (nn < N) {
        float s = 0.f;
        #pragma unroll
        for (int j = 0; j < 8; j++) s += red[j][m][lnn];
        s += bias[nn];
        if (RELU_OUT) s = fmaxf(s, 0.f);
        C[(ll)m * N + nn] = s;
    }
}

// ---------------- launch ------------------------------------------------------
extern "C" void kernel_launch(void* const* d_in, const int* in_sizes, int n_in,
                              void* d_out, int out_size)
{
    const float* in_pe  = (const float*)d_in[0];
    const float* in_pfx = (const float*)d_in[1];
    const float* in_cf  = (const float*)d_in[2];
    const float* emb_w = (const float*)d_in[3];  const float* emb_b = (const float*)d_in[4];
    const float* wq_w  = (const float*)d_in[5];  const float* wq_b  = (const float*)d_in[6];
    const float* wk_w  = (const float*)d_in[7];  const float* wk_b  = (const float*)d_in[8];
    const float* wv_w  = (const float*)d_in[9];  const float* wv_b  = (const float*)d_in[10];
    const float* wo_w  = (const float*)d_in[11]; const float* wo_b  = (const float*)d_in[12];
    const float* jp_w  = (const float*)d_in[13]; const float* jp_b  = (const float*)d_in[14];
    const float* jc_w  = (const float*)d_in[15]; const float* jc_b  = (const float*)d_in[16];
    const float* c1_w  = (const float*)d_in[17]; const float* c1_b  = (const float*)d_in[18];
    const float* c2_w  = (const float*)d_in[19]; const float* c2_b  = (const float*)d_in[20];
    const float* c3_w  = (const float*)d_in[21]; const float* c3_b  = (const float*)d_in[22];
    const float* c4_w  = (const float*)d_in[23]; const float* c4_b  = (const float*)d_in[24];

    uint2 *Qhl, *Khl, *Vhl, *Chl, *Wqhl, *wkhl, *wvhl, *wohl, *jphl, *jchl, *wqhl0;
    float *AV0, *AV1, *pf, *P, *S, *A, *bq, *Apart, *part, *cp, *h1, *h2, *h3;
    cudaGetSymbolAddress((void**)&Qhl,  g_Qhl);
    cudaGetSymbolAddress((void**)&Khl,  g_Khl);
    cudaGetSymbolAddress((void**)&Vhl,  g_Vhl);
    cudaGetSymbolAddress((void**)&Chl,  g_Chl);
    cudaGetSymbolAddress((void**)&Wqhl, g_Wqhl);
    cudaGetSymbolAddress((void**)&wkhl, g_wkhl);
    cudaGetSymbolAddress((void**)&wvhl, g_wvhl);
    cudaGetSymbolAddress((void**)&wohl, g_wohl);
    cudaGetSymbolAddress((void**)&jphl, g_jphl);
    cudaGetSymbolAddress((void**)&jchl, g_jchl);
    cudaGetSymbolAddress((void**)&wqhl0,g_wqhl0);
    cudaGetSymbolAddress((void**)&AV0,  g_AV0);
    cudaGetSymbolAddress((void**)&AV1,  g_AV1);
    cudaGetSymbolAddress((void**)&pf,   g_pf);
    cudaGetSymbolAddress((void**)&P,    g_P);
    cudaGetSymbolAddress((void**)&S,    g_S);
    cudaGetSymbolAddress((void**)&A,    g_A);
    cudaGetSymbolAddress((void**)&bq,   g_bq);
    cudaGetSymbolAddress((void**)&Apart,g_Apart);
    cudaGetSymbolAddress((void**)&part, g_part);
    cudaGetSymbolAddress((void**)&cp,   g_cp);
    cudaGetSymbolAddress((void**)&h1,   g_h1);
    cudaGetSymbolAddress((void**)&h2,   g_h2);
    cudaGetSymbolAddress((void**)&h3,   g_h3);

    const float inv_sqrt_d = 0.088388347648318440550f;  // 1/sqrt(128)

    // 0. weights -> hi/lo ; Wq' = emb_w @ wq_w ; bq'
    prep6_kernel<<<dim3(64,6),256>>>(wq_w, wk_w, wv_w, wo_w, jp_w, jc_w,
                                     wqhl0, wkhl, wvhl, wohl, jphl, jchl);
    gemm_wqp<<<dim3(1,5),256>>>(emb_w, wqhl0, Wqhl);
    fuse_bq_kernel<<<1,128>>>(emb_b, wq_w, wq_b, bq);
    // 1. Q/K/V (Q pre-scaled by 1/sqrt(D)), emitted as hi/lo
    gemm_qkv<<<dim3(1,125,3),256>>>(in_pe, Wqhl, bq, Qhl,
                                    in_pfx, wkhl, wk_b, Khl,
                                    wvhl, wv_b, Vhl, inv_sqrt_d);
    // 2. S = Qs @ K^T
    gemm_qk<<<dim3(8,16,B_),256>>>(Qhl, Khl, S);
    // 3. softmax
    softmax_kernel<<<B_*LP_,256>>>(S);
    // 4. AV split-K=2
    gemm_av<<<dim3(1,16,B_*2),256>>>(S, Vhl, AV0, AV1);
    // 5. pf = (AV0+AV1) @ wo + b   (combine fused into A-loader)
    gemm_wo<<<dim3(1,125),256>>>(AV0, AV1, wohl, wo_b, pf);
    // 6. P / Chl
    gemm_pc<<<dim3(1,125,2),256>>>(pf, jphl, jp_b, P, in_cf, jchl, jc_b, Chl);
    // 7. A = sigmoid(P @ C^T) + partial sums
    alogits_kernel<<<dim3(16,B_),256>>>(P, Chl, A, Apart);
    // 8. tanh outer product partials
    tanh_outer_kernel<<<dim3(NTILE_,B_),128>>>(pf, in_cf, A, part);
    // 9. reduce + normalize
    cp_reduce_kernel<<<B_,128>>>(part, Apart, cp);
    // 10-13. classifier MLP
    skinny_gemm<true ><<<32,256>>>(cp, c1_w, c1_b, h1, 1024, D_);
    skinny_gemm<true ><<<32,256>>>(h1, c2_w, c2_b, h2, 1024, 1024);
    skinny_gemm<true ><<<8, 256>>>(h2, c3_w, c3_b, h3, 256, 1024);
    skinny_gemm<false><<<1, 256>>>(h3, c4_w, c4_b, (float*)d_out, 1, 256);
}

// round 6
// speedup vs baseline: 1.4044x; 1.4044x over previous
#include <cuda_runtime.h>
#include <math.h>
#include <stdint.h>

#define B_  8
#define LP_ 1000
#define NC_ 64
#define D_  128
#define E_  320
#define NTILE_ 100
#define ITILE_ 10
typedef long long ll;

// ---------------- scratch (device globals) ----------------------------------
__device__ __align__(16) uint2 g_Qhl[B_*LP_*64];    // bf16 hi/lo pairs along d
__device__ __align__(16) uint2 g_Khl[B_*LP_*64];
__device__ __align__(16) uint2 g_Chl[B_*NC_*64];
__device__ __align__(16) uint2 g_wqp[64*D_];        // weights: [kp][n] pairs
__device__ __align__(16) uint2 g_wkp[64*D_];
__device__ __align__(16) uint2 g_wvp[64*D_];
__device__ __align__(16) uint2 g_wop[64*D_];
__device__ __align__(16) uint2 g_jpp[64*D_];
__device__ __align__(16) uint2 g_jcp[64*D_];
__device__ __align__(16) uint2 g_Wqp[160*D_];       // fused emb@wq, paired
__device__ __align__(16) float g_Wq0[E_*D_];
__device__ __align__(16) float g_Vf [B_*LP_*D_];
__device__ __align__(16) float g_AV0[B_*LP_*D_];
__device__ __align__(16) float g_AV1[B_*LP_*D_];
__device__ __align__(16) float g_pf [B_*LP_*D_];
__device__ __align__(16) float g_P  [B_*LP_*D_];
__device__ __align__(16) float g_S  [B_*LP_*LP_];
__device__ __align__(16) float g_A  [B_*LP_*NC_];
__device__ __align__(16) float g_bq [D_];
__device__ __align__(16) float g_Apart[B_*16];
__device__ __align__(16) float g_part[B_*NTILE_*D_];
__device__ __align__(16) float g_cp [B_*D_];
__device__ __align__(16) float g_h1 [B_*1024];
__device__ __align__(16) float g_h2 [B_*1024];
__device__ __align__(16) float g_h3 [B_*256];

// ---------------- bf16 helpers -----------------------------------------------
__device__ __forceinline__ uint32_t packbf(float x, float y) {  // lo=x, hi=y
    uint32_t r;
    asm("cvt.rn.bf16x2.f32 %0, %1, %2;" : "=r"(r) : "f"(y), "f"(x));
    return r;
}
__device__ __forceinline__ float lowbf(uint32_t h)  { return __uint_as_float(h << 16); }
__device__ __forceinline__ float highbf(uint32_t h) { return __uint_as_float(h & 0xFFFF0000u); }
// (hi,lo) packed pair for 2 consecutive reduction-axis elements
__device__ __forceinline__ uint2 cvt_pair(float x, float y) {
    uint32_t h = packbf(x, y);
    uint32_t l = packbf(x - lowbf(h), y - highbf(h));
    return make_uint2(h, l);
}
__device__ __forceinline__ void mma_bf16(float* d, const uint32_t* a, const uint32_t* b) {
    asm volatile(
        "mma.sync.aligned.m16n8k16.row.col.f32.bf16.bf16.f32 "
        "{%0,%1,%2,%3}, {%4,%5,%6,%7}, {%8,%9}, {%0,%1,%2,%3};\n"
        : "+f"(d[0]), "+f"(d[1]), "+f"(d[2]), "+f"(d[3])
        : "r"(a[0]), "r"(a[1]), "r"(a[2]), "r"(a[3]), "r"(b[0]), "r"(b[1]));
}

// ---------------- unified GEMM body: 64(M) x 128(N) tile, BK=16, bf16x3 -----
// AMODE: 0=A fp32 cvt, 1=fp32+relu, 2=A pre-paired uint2, 3=dual fp32 add
// BMODE: 0=pre-paired, 1=fp32 nontrans pack-on-fly (V)
// EPI: 0=fp32 out, 1=pair uint2 out.  GUARD: K-tail bounds (av 2nd half).
// smem (uint2 = one k-pair hi/lo): A [m][kp] pitch 12; trans-B [n][kp] 12;
// non-trans B [kp][n] pitch 132.
template<int AMODE, int BMODE, bool TRANS_B, int EPI, bool GUARD>
__device__ __forceinline__ void gemm_body(
    const float* __restrict__ Af, const float* __restrict__ Af2,
    const uint2* __restrict__ Ah,
    const uint2* __restrict__ Bh, const float* __restrict__ Bf,
    const float* __restrict__ bias, float* __restrict__ Cf, uint2* __restrict__ Ch,
    int M, int N, int K, int lda, int ldb,
    float alpha, int m0, int n0, uint2* As, uint2* Bs)
{
    constexpr int ASN = 64 * 12;
    constexpr int BSN = TRANS_B ? 128 * 12 : 8 * 132;

    int t = threadIdx.x, warp = t >> 5, lane = t & 31;
    int g = lane >> 2, l3 = lane & 3;
    int wm = (warp & 1) * 32, wn = (warp >> 1) * 32;

    float acc[2][4][4] = {};

    int ar = t >> 2, akf = (t & 3) * 4, akp = (t & 3) * 2;  // A loader
    int btr = t >> 1, btp = (t & 1) * 4;                    // trans-B loader
    int bk = t >> 5, bn = (t & 31) * 4;                     // non-trans loader

    int kt = GUARD ? ((K + 15) >> 4) : (K >> 4);
    uint4 ua, ub0, ub1;

    auto loadA = [&](int k0) {
        int gm = m0 + ar;
        if (AMODE == 2) {
            ua = make_uint4(0u, 0u, 0u, 0u);
            if (gm < M) ua = *(const uint4*)(Ah + (ll)gm * (lda >> 1) + (k0 >> 1) + akp);
        } else {
            float4 rv = make_float4(0.f, 0.f, 0.f, 0.f);
            if (gm < M) {
                int gk = k0 + akf;
                if (!GUARD || gk + 3 < K) {
                    rv = *(const float4*)(Af + (ll)gm * lda + gk);
                    if (AMODE == 3) {
                        float4 r2 = *(const float4*)(Af2 + (ll)gm * lda + gk);
                        rv.x += r2.x; rv.y += r2.y; rv.z += r2.z; rv.w += r2.w;
                    }
                } else {
                    const float* bp = Af + (ll)gm * lda;
                    rv.x = (gk     < K) ? bp[gk]     : 0.f;
                    rv.y = (gk + 1 < K) ? bp[gk + 1] : 0.f;
                    rv.z = (gk + 2 < K) ? bp[gk + 2] : 0.f;
                    rv.w = (gk + 3 < K) ? bp[gk + 3] : 0.f;
                }
                if (AMODE == 1) {
                    rv.x = fmaxf(rv.x, 0.f); rv.y = fmaxf(rv.y, 0.f);
                    rv.z = fmaxf(rv.z, 0.f); rv.w = fmaxf(rv.w, 0.f);
                }
            }
            uint2 p0 = cvt_pair(rv.x, rv.y), p1 = cvt_pair(rv.z, rv.w);
            ua = make_uint4(p0.x, p0.y, p1.x, p1.y);
        }
    };
    auto loadB = [&](int k0) {
        if (TRANS_B) {
            int gn = n0 + btr;
            ub0 = make_uint4(0u, 0u, 0u, 0u); ub1 = ub0;
            if (gn < N) {
                const uint2* p = Bh + (ll)gn * (K >> 1) + (k0 >> 1) + btp;
                ub0 = *(const uint4*)p;
                ub1 = *(const uint4*)(p + 2);
            }
        } else if (BMODE == 0) {
            const uint2* p = Bh + (ll)((k0 >> 1) + bk) * N + bn;
            ub0 = *(const uint4*)p;
            ub1 = *(const uint4*)(p + 2);
        } else {  // fp32 V: pack rows 2kp, 2kp+1 on the fly
            int gk0 = k0 + 2 * bk, gk1 = gk0 + 1;
            float4 r0 = make_float4(0.f, 0.f, 0.f, 0.f), r1 = r0;
            if (!GUARD || gk0 < K) r0 = *(const float4*)(Bf + (ll)gk0 * ldb + bn);
            if (!GUARD || gk1 < K) r1 = *(const float4*)(Bf + (ll)gk1 * ldb + bn);
            uint2 q0 = cvt_pair(r0.x, r1.x), q1 = cvt_pair(r0.y, r1.y);
            uint2 q2 = cvt_pair(r0.z, r1.z), q3 = cvt_pair(r0.w, r1.w);
            ub0 = make_uint4(q0.x, q0.y, q1.x, q1.y);
            ub1 = make_uint4(q2.x, q2.y, q3.x, q3.y);
        }
    };
    auto storeA = [&](int s) { *(uint4*)&As[s * ASN + ar * 12 + akp] = ua; };
    auto storeB = [&](int s) {
        if (TRANS_B) {
            *(uint4*)&Bs[s * BSN + btr * 12 + btp]     = ub0;
            *(uint4*)&Bs[s * BSN + btr * 12 + btp + 2] = ub1;
        } else {
            *(uint4*)&Bs[s * BSN + bk * 132 + bn]     = ub0;
            *(uint4*)&Bs[s * BSN + bk * 132 + bn + 2] = ub1;
        }
    };

    loadA(0); loadB(0);
    storeA(0); storeB(0);
    __syncthreads();

    for (int it = 0; it < kt; it++) {
        int s = it & 1;
        if (it + 1 < kt) { loadA((it + 1) << 4); loadB((it + 1) << 4); }

        uint32_t ahi[2][4], alo[2][4];
        #pragma unroll
        for (int mi = 0; mi < 2; mi++) {
            int rr = wm + mi * 16 + g;
            uint2 x0 = As[s * ASN + rr * 12 + l3];
            uint2 x1 = As[s * ASN + (rr + 8) * 12 + l3];
            uint2 x2 = As[s * ASN + rr * 12 + l3 + 4];
            uint2 x3 = As[s * ASN + (rr + 8) * 12 + l3 + 4];
            ahi[mi][0] = x0.x; alo[mi][0] = x0.y;
            ahi[mi][1] = x1.x; alo[mi][1] = x1.y;
            ahi[mi][2] = x2.x; alo[mi][2] = x2.y;
            ahi[mi][3] = x3.x; alo[mi][3] = x3.y;
        }
        uint32_t bhi[4][2], blo[4][2];
        #pragma unroll
        for (int ni = 0; ni < 4; ni++) {
            int cc = wn + ni * 8 + g;
            uint2 y0 = TRANS_B ? Bs[s * BSN + cc * 12 + l3]
                               : Bs[s * BSN + l3 * 132 + cc];
            uint2 y1 = TRANS_B ? Bs[s * BSN + cc * 12 + l3 + 4]
                               : Bs[s * BSN + (l3 + 4) * 132 + cc];
            bhi[ni][0] = y0.x; blo[ni][0] = y0.y;
            bhi[ni][1] = y1.x; blo[ni][1] = y1.y;
        }
        #pragma unroll
        for (int mi = 0; mi < 2; mi++)
            #pragma unroll
            for (int ni = 0; ni < 4; ni++) {
                mma_bf16(acc[mi][ni], ahi[mi], bhi[ni]);
                mma_bf16(acc[mi][ni], ahi[mi], blo[ni]);
                mma_bf16(acc[mi][ni], alo[mi], bhi[ni]);
            }
        if (it + 1 < kt) { storeA(s ^ 1); storeB(s ^ 1); }
        __syncthreads();
    }

    #pragma unroll
    for (int mi = 0; mi < 2; mi++)
        #pragma unroll
        for (int ni = 0; ni < 4; ni++) {
            int r0 = m0 + wm + mi * 16 + g;
            int c0 = n0 + wn + ni * 8 + 2 * l3;
            if (c0 >= N) continue;
            float b0 = 0.f, b1 = 0.f;
            if (bias) { b0 = bias[c0]; b1 = bias[c0 + 1]; }
            float v00 = (acc[mi][ni][0] + b0) * alpha;
            float v01 = (acc[mi][ni][1] + b1) * alpha;
            float v10 = (acc[mi][ni][2] + b0) * alpha;
            float v11 = (acc[mi][ni][3] + b1) * alpha;
            if (EPI == 0) {
                if (r0 < M)     *(float2*)(Cf + (ll)r0 * N + c0)       = make_float2(v00, v01);
                if (r0 + 8 < M) *(float2*)(Cf + (ll)(r0 + 8) * N + c0) = make_float2(v10, v11);
            } else {
                if (r0 < M)     Ch[(ll)r0 * (N >> 1) + (c0 >> 1)]       = cvt_pair(v00, v01);
                if (r0 + 8 < M) Ch[(ll)(r0 + 8) * (N >> 1) + (c0 >> 1)] = cvt_pair(v10, v11);
            }
        }
}

// ---------------- wrappers ----------------------------------------------------
// repack fp32 [K][N] -> [K/2][N] uint2 pairs (pairs along K)
__global__ void repack_kernel(const float* __restrict__ W, uint2* __restrict__ O,
                              int N, int total)
{
    int i = blockIdx.x * 256 + threadIdx.x;
    if (i >= total) return;
    int kp = i / N, n = i - kp * N;
    O[i] = cvt_pair(W[(ll)(2 * kp) * N + n], W[(ll)(2 * kp + 1) * N + n]);
}
__global__ void prep6_kernel(const float* w0, const float* w1, const float* w2,
                             const float* w3, const float* w4, const float* w5,
                             uint2* d0, uint2* d1, uint2* d2,
                             uint2* d3, uint2* d4, uint2* d5)
{
    int i = blockIdx.x * 256 + threadIdx.x;   // 0..8191
    const float* s; uint2* d;
    switch (blockIdx.y) {
        case 0: s = w0; d = d0; break;
        case 1: s = w1; d = d1; break;
        case 2: s = w2; d = d2; break;
        case 3: s = w3; d = d3; break;
        case 4: s = w4; d = d4; break;
        default: s = w5; d = d5; break;
    }
    int kp = i >> 7, n = i & 127;
    d[i] = cvt_pair(s[(2 * kp) * D_ + n], s[(2 * kp + 1) * D_ + n]);
}

// Wq0 = emb_w @ wq_w (fp32 out; repacked separately)
__global__ void __launch_bounds__(256, 2)
gemm_wqp(const float* __restrict__ emb_w, const uint2* __restrict__ wqp,
         float* __restrict__ Wq0)
{
    __shared__ __align__(16) uint2 As[2 * 64 * 12];
    __shared__ __align__(16) uint2 Bs[2 * 8 * 132];
    gemm_body<0, 0, false, 0, false>(emb_w, nullptr, nullptr, wqp, nullptr,
        nullptr, Wq0, nullptr, E_, D_, D_, D_, D_, 1.f, blockIdx.y * 64, 0, As, Bs);
}

__global__ void __launch_bounds__(256, 2)
gemm_qkv(const float* __restrict__ in_pe, const uint2* __restrict__ Wqp,
         const float* __restrict__ bq, uint2* __restrict__ Qhl,
         const float* __restrict__ in_pfx,
         const uint2* __restrict__ wkp, const float* __restrict__ wk_b,
         uint2* __restrict__ Khl,
         const uint2* __restrict__ wvp, const float* __restrict__ wv_b,
         float* __restrict__ Vf, float inv_sqrt_d)
{
    __shared__ __align__(16) uint2 As[2 * 64 * 12];
    __shared__ __align__(16) uint2 Bs[2 * 8 * 132];
    int m0 = blockIdx.y * 64;
    if (blockIdx.z == 0)
        gemm_body<0, 0, false, 1, false>(in_pe, nullptr, nullptr, Wqp, nullptr,
            bq, nullptr, Qhl, B_*LP_, D_, E_, E_, D_, inv_sqrt_d, m0, 0, As, Bs);
    else if (blockIdx.z == 1)
        gemm_body<0, 0, false, 1, false>(in_pfx, nullptr, nullptr, wkp, nullptr,
            wk_b, nullptr, Khl, B_*LP_, D_, D_, D_, D_, 1.f, m0, 0, As, Bs);
    else
        gemm_body<0, 0, false, 0, false>(in_pfx, nullptr, nullptr, wvp, nullptr,
            wv_b, Vf, nullptr, B_*LP_, D_, D_, D_, D_, 1.f, m0, 0, As, Bs);
}

// S = Qs @ K^T (scale folded into Q)
__global__ void __launch_bounds__(256, 2)
gemm_qk(const uint2* __restrict__ Qhl, const uint2* __restrict__ Khl,
        float* __restrict__ S)
{
    __shared__ __align__(16) uint2 As[2 * 64 * 12];
    __shared__ __align__(16) uint2 Bs[2 * 128 * 12];
    int b = blockIdx.z;
    gemm_body<2, 0, true, 0, false>(nullptr, nullptr,
        Qhl + (ll)b * LP_ * 64, Khl + (ll)b * LP_ * 64, nullptr, nullptr,
        S + (ll)b * LP_ * LP_, nullptr,
        LP_, LP_, D_, D_, D_, 1.f, blockIdx.y * 64, blockIdx.x * 128, As, Bs);
}

// AV split-K=2; V fp32 packed on the fly
__global__ void __launch_bounds__(256, 2)
gemm_av(const float* __restrict__ S, const float* __restrict__ Vf,
        float* __restrict__ AV0, float* __restrict__ AV1)
{
    __shared__ __align__(16) uint2 As[2 * 64 * 12];
    __shared__ __align__(16) uint2 Bs[2 * 8 * 132];
    int b = blockIdx.z >> 1, half = blockIdx.z & 1;
    if (half == 0)
        gemm_body<0, 1, false, 0, false>(
            S + (ll)b * LP_ * LP_, nullptr, nullptr, nullptr,
            Vf + (ll)b * LP_ * D_, nullptr,
            AV0 + (ll)b * LP_ * D_, nullptr,
            LP_, D_, 512, LP_, D_, 1.f, blockIdx.y * 64, 0, As, Bs);
    else
        gemm_body<0, 1, false, 0, true>(
            S + (ll)b * LP_ * LP_ + 512, nullptr, nullptr, nullptr,
            Vf + ((ll)b * LP_ + 512) * D_, nullptr,
            AV1 + (ll)b * LP_ * D_, nullptr,
            LP_, D_, 488, LP_, D_, 1.f, blockIdx.y * 64, 0, As, Bs);
}

// pf = (AV0+AV1) @ wo + b
__global__ void __launch_bounds__(256, 2)
gemm_wo(const float* __restrict__ AV0, const float* __restrict__ AV1,
        const uint2* __restrict__ wop, const float* __restrict__ wo_b,
        float* __restrict__ pf)
{
    __shared__ __align__(16) uint2 As[2 * 64 * 12];
    __shared__ __align__(16) uint2 Bs[2 * 8 * 132];
    gemm_body<3, 0, false, 0, false>(AV0, AV1, nullptr, wop, nullptr,
        wo_b, pf, nullptr, B_*LP_, D_, D_, D_, D_, 1.f, blockIdx.y * 64, 0, As, Bs);
}

// P = relu(pf)@jp + b (fp32) ; Chl = relu(cf)@jc + b (pairs)
__global__ void __launch_bounds__(256, 2)
gemm_pc(const float* __restrict__ pf, const uint2* __restrict__ jpp,
        const float* __restrict__ jp_b, float* __restrict__ P,
        const float* __restrict__ cf, const uint2* __restrict__ jcp,
        const float* __restrict__ jc_b, uint2* __restrict__ Chl)
{
    if (blockIdx.z == 1 && blockIdx.y >= 8) return;
    __shared__ __align__(16) uint2 As[2 * 64 * 12];
    __shared__ __align__(16) uint2 Bs[2 * 8 * 132];
    int m0 = blockIdx.y * 64;
    if (blockIdx.z == 0)
        gemm_body<1, 0, false, 0, false>(pf, nullptr, nullptr, jpp, nullptr,
            jp_b, P, nullptr, B_*LP_, D_, D_, D_, D_, 1.f, m0, 0, As, Bs);
    else
        gemm_body<1, 0, false, 1, false>(cf, nullptr, nullptr, jcp, nullptr,
            jc_b, nullptr, Chl, B_*NC_, D_, D_, D_, D_, 1.f, m0, 0, As, Bs);
}

// ---------------- A-logits: bf16x3 64x64 GEMM + sigmoid + partial sums -------
__global__ void __launch_bounds__(256, 2)
alogits_kernel(const float* __restrict__ Pm, const uint2* __restrict__ Chl,
               float* __restrict__ Aout, float* __restrict__ Apart)
{
    __shared__ __align__(16) uint2 As[2][768];
    __shared__ __align__(16) uint2 Bs[2][768];
    __shared__ float red[256];

    int b = blockIdx.y, mt = blockIdx.x, m0 = mt * 64;
    const float* A = Pm + (ll)b * LP_ * D_;
    const uint2* Bh = Chl + (ll)b * NC_ * 64;
    float* C = Aout + (ll)b * LP_ * NC_;
    int t = threadIdx.x, warp = t >> 5, lane = t & 31;
    int g = lane >> 2, l3 = lane & 3;
    int wm = (warp & 1) * 32, wn = (warp >> 1) * 16;

    float acc[2][2][4] = {};
    int ar = t >> 2, akf = (t & 3) * 4, akp = (t & 3) * 2;
    uint4 ua, ub;

    auto loadAB = [&](int k0) {
        int gm = m0 + ar;
        float4 rv = make_float4(0.f, 0.f, 0.f, 0.f);
        if (gm < LP_) rv = *(const float4*)(A + (ll)gm * D_ + k0 + akf);
        uint2 p0 = cvt_pair(rv.x, rv.y), p1 = cvt_pair(rv.z, rv.w);
        ua = make_uint4(p0.x, p0.y, p1.x, p1.y);
        ub = *(const uint4*)(Bh + (ll)ar * 64 + (k0 >> 1) + akp);
    };
    auto storeAB = [&](int s) {
        *(uint4*)&As[s][ar * 12 + akp] = ua;
        *(uint4*)&Bs[s][ar * 12 + akp] = ub;
    };
    loadAB(0); storeAB(0);
    __syncthreads();

    for (int it = 0; it < 8; it++) {
        int s = it & 1;
        if (it < 7) loadAB((it + 1) << 4);
        uint32_t ahi[2][4], alo[2][4];
        #pragma unroll
        for (int mi = 0; mi < 2; mi++) {
            int rr = wm + mi * 16 + g;
            uint2 x0 = As[s][rr * 12 + l3];
            uint2 x1 = As[s][(rr + 8) * 12 + l3];
            uint2 x2 = As[s][rr * 12 + l3 + 4];
            uint2 x3 = As[s][(rr + 8) * 12 + l3 + 4];
            ahi[mi][0] = x0.x; alo[mi][0] = x0.y;
            ahi[mi][1] = x1.x; alo[mi][1] = x1.y;
            ahi[mi][2] = x2.x; alo[mi][2] = x2.y;
            ahi[mi][3] = x3.x; alo[mi][3] = x3.y;
        }
        uint32_t bhi[2][2], blo[2][2];
        #pragma unroll
        for (int ni = 0; ni < 2; ni++) {
            int cc = wn + ni * 8 + g;
            uint2 y0 = Bs[s][cc * 12 + l3];
            uint2 y1 = Bs[s][cc * 12 + l3 + 4];
            bhi[ni][0] = y0.x; blo[ni][0] = y0.y;
            bhi[ni][1] = y1.x; blo[ni][1] = y1.y;
        }
        #pragma unroll
        for (int mi = 0; mi < 2; mi++)
            #pragma unroll
            for (int ni = 0; ni < 2; ni++) {
                mma_bf16(acc[mi][ni], ahi[mi], bhi[ni]);
                mma_bf16(acc[mi][ni], ahi[mi], blo[ni]);
                mma_bf16(acc[mi][ni], alo[mi], bhi[ni]);
            }
        if (it < 7) storeAB(s ^ 1);
        __syncthreads();
    }

    float tsum = 0.f;
    #pragma unroll
    for (int mi = 0; mi < 2; mi++)
        #pragma unroll
        for (int ni = 0; ni < 2; ni++) {
            int r0 = m0 + wm + mi * 16 + g;
            int c0 = wn + ni * 8 + 2 * l3;
            if (r0 < LP_) {
                float v0 = 1.f / (1.f + __expf(-acc[mi][ni][0]));
                float v1 = 1.f / (1.f + __expf(-acc[mi][ni][1]));
                *(float2*)(C + (ll)r0 * NC_ + c0) = make_float2(v0, v1);
                tsum += v0 + v1;
            }
            if (r0 + 8 < LP_) {
                float v0 = 1.f / (1.f + __expf(-acc[mi][ni][2]));
                float v1 = 1.f / (1.f + __expf(-acc[mi][ni][3]));
                *(float2*)(C + (ll)(r0 + 8) * NC_ + c0) = make_float2(v0, v1);
                tsum += v0 + v1;
            }
        }
    red[t] = tsum; __syncthreads();
    for (int s2 = 128; s2 > 0; s2 >>= 1) {
        if (t < s2) red[t] += red[t + s2];
        __syncthreads();
    }
    if (t == 0) Apart[b * 16 + mt] = red[0];
}

// ---------------- bq' = emb_b @ wq_w + wq_b ---------------------------------
__global__ void fuse_bq_kernel(const float* __restrict__ emb_b,
                               const float* __restrict__ wq_w,
                               const float* __restrict__ wq_b,
                               float* __restrict__ bq)
{
    int n = threadIdx.x;
    float s = wq_b[n];
    for (int k = 0; k < D_; k++) s = fmaf(emb_b[k], wq_w[k * D_ + n], s);
    bq[n] = s;
}

// ---------------- row softmax (float4 + shuffle) ------------------------------
__global__ void softmax_kernel(float* __restrict__ S)
{
    ll row = blockIdx.x;
    float* p = S + row * LP_;
    int t = threadIdx.x;  // 256
    __shared__ float sm[8], sm2[8];
    bool act = t < 250;
    float4 v = make_float4(-1e30f, -1e30f, -1e30f, -1e30f);
    if (act) v = *(float4*)(p + t * 4);
    float mx = fmaxf(fmaxf(v.x, v.y), fmaxf(v.z, v.w));
    #pragma unroll
    for (int o = 16; o > 0; o >>= 1) mx = fmaxf(mx, __shfl_xor_sync(0xffffffffu, mx, o));
    if ((t & 31) == 0) sm[t >> 5] = mx;
    __syncthreads();
    mx = sm[0];
    #pragma unroll
    for (int j = 1; j < 8; j++) mx = fmaxf(mx, sm[j]);
    v.x = __expf(v.x - mx); v.y = __expf(v.y - mx);
    v.z = __expf(v.z - mx); v.w = __expf(v.w - mx);
    float s = v.x + v.y + v.z + v.w;
    #pragma unroll
    for (int o = 16; o > 0; o >>= 1) s += __shfl_xor_sync(0xffffffffu, s, o);
    if ((t & 31) == 0) sm2[t >> 5] = s;
    __syncthreads();
    s = sm2[0] + sm2[1] + sm2[2] + sm2[3] + sm2[4] + sm2[5] + sm2[6] + sm2[7];
    float inv = 1.f / s;
    if (act) {
        v.x *= inv; v.y *= inv; v.z *= inv; v.w *= inv;
        *(float4*)(p + t * 4) = v;
    }
}

// ---------------- tanh outer-product weighted reduction ---------------------
__global__ void tanh_outer_kernel(const float* __restrict__ pf,
                                  const float* __restrict__ cf,
                                  const float* __restrict__ A,
                                  float* __restrict__ part)
{
    int b = blockIdx.y, tile = blockIdx.x;
    int d = threadIdx.x;  // 128
    __shared__ float cfs[NC_ * D_];
    for (int i = threadIdx.x; i < NC_ * D_; i += 128)
        cfs[i] = cf[(ll)b * NC_ * D_ + i];
    __syncthreads();
    float acc = 0.f;
    int i0 = tile * ITILE_;
    for (int i = i0; i < i0 + ITILE_; i++) {
        float pv = pf[((ll)b * LP_ + i) * D_ + d];
        const float* Ar = A + ((ll)b * LP_ + i) * NC_;
        #pragma unroll 4
        for (int k = 0; k < NC_; k++) {
            float w = Ar[k];
            float x = pv * cfs[k * D_ + d];
            float th;
            asm("tanh.approx.f32 %0, %1;" : "=f"(th) : "f"(x));
            acc = fmaf(th, w, acc);
        }
    }
    part[((ll)b * NTILE_ + tile) * D_ + d] = acc;
}

__global__ void cp_reduce_kernel(const float* __restrict__ part,
                                 const float* __restrict__ Apart,
                                 float* __restrict__ cp)
{
    int b = blockIdx.x;
    int d = threadIdx.x;  // 128
    float as = 0.f;
    #pragma unroll
    for (int j = 0; j < 16; j++) as += Apart[b * 16 + j];
    float s = 0.f;
    for (int t2 = 0; t2 < NTILE_; t2++)
        s += part[((ll)b * NTILE_ + t2) * D_ + d];
    cp[b * D_ + d] = s / as;
}

// ---------------- skinny GEMM (M = 8 rows) -----------------------------------
template<bool RELU_OUT>
__global__ void __launch_bounds__(256)
skinny_gemm(const float* __restrict__ A, const float* __restrict__ W,
            const float* __restrict__ bias, float* __restrict__ C,
            int N, int K)
{
    __shared__ float As[8 * 1024];
    __shared__ float red[8][8][32];
    int t = threadIdx.x;
    for (int i = t; i < 8 * K; i += 256) As[i] = A[i];
    __syncthreads();
    int n = blockIdx.x * 32 + (t & 31);
    int ks = t >> 5;
    int kseg = K >> 3;
    float acc[8] = {};
    if (n < N) {
        for (int k = ks * kseg; k < (ks + 1) * kseg; k++) {
            float w = W[(ll)k * N + n];
            #pragma unroll
            for (int m = 0; m < 8; m++) acc[m] = fmaf(As[m * K + k], w, acc[m]);
        }
    }
    #pragma unroll
    for (int m = 0; m < 8; m++) red[ks][m][t & 31] = acc[m];
    __syncthreads();
    int m = t >> 5, lnn = t & 31;
    int nn = blockIdx.x * 32 + lnn;
    if (nn < N) {
        float s = 0.f;
        #pragma unroll
        for (int j = 0; j < 8; j++) s += red[j][m][lnn];
        s += bias[nn];
        if (RELU_OUT) s = fmaxf(s, 0.f);
        C[(ll)m * N + nn] = s;
    }
}

// ---------------- launch ------------------------------------------------------
extern "C" void kernel_launch(void* const* d_in, const int* in_sizes, int n_in,
                              void* d_out, int out_size)
{
    const float* in_pe  = (const float*)d_in[0];
    const float* in_pfx = (const float*)d_in[1];
    const float* in_cf  = (const float*)d_in[2];
    const float* emb_w = (const float*)d_in[3];  const float* emb_b = (const float*)d_in[4];
    const float* wq_w  = (const float*)d_in[5];  const float* wq_b  = (const float*)d_in[6];
    const float* wk_w  = (const float*)d_in[7];  const float* wk_b  = (const float*)d_in[8];
    const float* wv_w  = (const float*)d_in[9];  const float* wv_b  = (const float*)d_in[10];
    const float* wo_w  = (const float*)d_in[11]; const float* wo_b  = (const float*)d_in[12];
    const float* jp_w  = (const float*)d_in[13]; const float* jp_b  = (const float*)d_in[14];
    const float* jc_w  = (const float*)d_in[15]; const float* jc_b  = (const float*)d_in[16];
    const float* c1_w  = (const float*)d_in[17]; const float* c1_b  = (const float*)d_in[18];
    const float* c2_w  = (const float*)d_in[19]; const float* c2_b  = (const float*)d_in[20];
    const float* c3_w  = (const float*)d_in[21]; const float* c3_b  = (const float*)d_in[22];
    const float* c4_w  = (const float*)d_in[23]; const float* c4_b  = (const float*)d_in[24];

    uint2 *Qhl, *Khl, *Chl, *wqp, *wkp, *wvp, *wop, *jpp, *jcp, *Wqp;
    float *Wq0, *Vf, *AV0, *AV1, *pf, *P, *S, *A, *bq, *Apart, *part, *cp, *h1, *h2, *h3;
    cudaGetSymbolAddress((void**)&Qhl,  g_Qhl);
    cudaGetSymbolAddress((void**)&Khl,  g_Khl);
    cudaGetSymbolAddress((void**)&Chl,  g_Chl);
    cudaGetSymbolAddress((void**)&wqp,  g_wqp);
    cudaGetSymbolAddress((void**)&wkp,  g_wkp);
    cudaGetSymbolAddress((void**)&wvp,  g_wvp);
    cudaGetSymbolAddress((void**)&wop,  g_wop);
    cudaGetSymbolAddress((void**)&jpp,  g_jpp);
    cudaGetSymbolAddress((void**)&jcp,  g_jcp);
    cudaGetSymbolAddress((void**)&Wqp,  g_Wqp);
    cudaGetSymbolAddress((void**)&Wq0,  g_Wq0);
    cudaGetSymbolAddress((void**)&Vf,   g_Vf);
    cudaGetSymbolAddress((void**)&AV0,  g_AV0);
    cudaGetSymbolAddress((void**)&AV1,  g_AV1);
    cudaGetSymbolAddress((void**)&pf,   g_pf);
    cudaGetSymbolAddress((void**)&P,    g_P);
    cudaGetSymbolAddress((void**)&S,    g_S);
    cudaGetSymbolAddress((void**)&A,    g_A);
    cudaGetSymbolAddress((void**)&bq,   g_bq);
    cudaGetSymbolAddress((void**)&Apart,g_Apart);
    cudaGetSymbolAddress((void**)&part, g_part);
    cudaGetSymbolAddress((void**)&cp,   g_cp);
    cudaGetSymbolAddress((void**)&h1,   g_h1);
    cudaGetSymbolAddress((void**)&h2,   g_h2);
    cudaGetSymbolAddress((void**)&h3,   g_h3);

    const float inv_sqrt_d = 0.088388347648318440550f;  // 1/sqrt(128)

    // 0. weights -> bf16 pairs; Wq' = emb_w @ wq_w; bq'
    prep6_kernel<<<dim3(32,6),256>>>(wq_w, wk_w, wv_w, wo_w, jp_w, jc_w,
                                     wqp, wkp, wvp, wop, jpp, jcp);
    fuse_bq_kernel<<<1,128>>>(emb_b, wq_w, wq_b, bq);
    gemm_wqp<<<dim3(1,5),256>>>(emb_w, wqp, Wq0);
    repack_kernel<<<80,256>>>(Wq0, Wqp, D_, 160 * D_);
    // 1. Q/K/V (Q pre-scaled; Q,K as pairs, V fp32)
    gemm_qkv<<<dim3(1,125,3),256>>>(in_pe, Wqp, bq, Qhl,
                                    in_pfx, wkp, wk_b, Khl,
                                    wvp, wv_b, Vf, inv_sqrt_d);
    // 2. S = Qs @ K^T
    gemm_qk<<<dim3(8,16,B_),256>>>(Qhl, Khl, S);
    // 3. softmax
    softmax_kernel<<<B_*LP_,256>>>(S);
    // 4. AV split-K=2
    gemm_av<<<dim3(1,16,B_*2),256>>>(S, Vf, AV0, AV1);
    // 5. pf = (AV0+AV1) @ wo + b
    gemm_wo<<<dim3(1,125),256>>>(AV0, AV1, wop, wo_b, pf);
    // 6. P / Chl
    gemm_pc<<<dim3(1,125,2),256>>>(pf, jpp, jp_b, P, in_cf, jcp, jc_b, Chl);
    // 7. A = sigmoid(P @ C^T) + partial sums
    alogits_kernel<<<dim3(16,B_),256>>>(P, Chl, A, Apart);
    // 8. tanh outer product partials
    tanh_outer_kernel<<<dim3(NTILE_,B_),128>>>(pf, in_cf, A, part);
    // 9. reduce + normalize
    cp_reduce_kernel<<<B_,128>>>(part, Apart, cp);
    // 10-13. classifier MLP
    skinny_gemm<true ><<<32,256>>>(cp, c1_w, c1_b, h1, 1024, D_);
    skinny_gemm<true ><<<32,256>>>(h1, c2_w, c2_b, h2, 1024, 1024);
    skinny_gemm<true ><<<8, 256>>>(h2, c3_w, c3_b, h3, 256, 1024);
    skinny_gemm<false><<<1, 256>>>(h3, c4_w, c4_b, (float*)d_out, 1, 256);
}

// round 8
// speedup vs baseline: 1.5027x; 1.0700x over previous
#include <cuda_runtime.h>
#include <math.h>
#include <stdint.h>

#define B_  8
#define LP_ 1000
#define NC_ 64
#define D_  128
#define E_  320
#define NTILE_ 100
#define ITILE_ 10
typedef long long ll;

// ---------------- scratch (device globals) ----------------------------------
__device__ __align__(16) uint2 g_Qhl[B_*LP_*64];    // bf16 hi/lo pairs along d
__device__ __align__(16) uint2 g_Khl[B_*LP_*64];
__device__ __align__(16) uint2 g_Chl[B_*NC_*64];
__device__ __align__(16) uint2 g_wqp[64*D_];        // weights: [kp][n] pairs
__device__ __align__(16) uint2 g_wkp[64*D_];
__device__ __align__(16) uint2 g_wvp[64*D_];
__device__ __align__(16) uint2 g_wop[64*D_];
__device__ __align__(16) uint2 g_jpp[64*D_];
__device__ __align__(16) uint2 g_jcp[64*D_];
__device__ __align__(16) uint2 g_Wqp[160*D_];
__device__ __align__(16) float g_Wq0[E_*D_];
__device__ __align__(16) float g_Vf [B_*LP_*D_];
__device__ __align__(16) float g_AV [B_*LP_*D_];
__device__ __align__(16) float g_pf [B_*LP_*D_];
__device__ __align__(16) float g_P  [B_*LP_*D_];
__device__ __align__(16) float g_A  [B_*LP_*NC_];
__device__ __align__(16) float g_bq [D_];
__device__ __align__(16) float g_Apart[B_*16];
__device__ __align__(16) float g_part[B_*NTILE_*D_];
__device__ __align__(16) float g_cp [B_*D_];
__device__ __align__(16) float g_h1 [B_*1024];
__device__ __align__(16) float g_h2 [B_*1024];
__device__ __align__(16) float g_h3 [B_*256];

// ---------------- bf16 helpers -----------------------------------------------
__device__ __forceinline__ uint32_t packbf(float x, float y) {  // lo=x, hi=y
    uint32_t r;
    asm("cvt.rn.bf16x2.f32 %0, %1, %2;" : "=r"(r) : "f"(y), "f"(x));
    return r;
}
__device__ __forceinline__ float lowbf(uint32_t h)  { return __uint_as_float(h << 16); }
__device__ __forceinline__ float highbf(uint32_t h) { return __uint_as_float(h & 0xFFFF0000u); }
__device__ __forceinline__ uint2 cvt_pair(float x, float y) {
    uint32_t h = packbf(x, y);
    uint32_t l = packbf(x - lowbf(h), y - highbf(h));
    return make_uint2(h, l);
}
__device__ __forceinline__ void mma_bf16(float* d, const uint32_t* a, const uint32_t* b) {
    asm volatile(
        "mma.sync.aligned.m16n8k16.row.col.f32.bf16.bf16.f32 "
        "{%0,%1,%2,%3}, {%4,%5,%6,%7}, {%8,%9}, {%0,%1,%2,%3};\n"
        : "+f"(d[0]), "+f"(d[1]), "+f"(d[2]), "+f"(d[3])
        : "r"(a[0]), "r"(a[1]), "r"(a[2]), "r"(a[3]), "r"(b[0]), "r"(b[1]));
}

// ---------------- unified GEMM body: 64(M) x 128(N) tile, BK=16, bf16x3 -----
template<int AMODE, int BMODE, bool TRANS_B, int EPI, bool GUARD>
__device__ __forceinline__ void gemm_body(
    const float* __restrict__ Af, const float* __restrict__ Af2,
    const uint2* __restrict__ Ah,
    const uint2* __restrict__ Bh, const float* __restrict__ Bf,
    const float* __restrict__ bias, float* __restrict__ Cf, uint2* __restrict__ Ch,
    int M, int N, int K, int lda, int ldb,
    float alpha, int m0, int n0, uint2* As, uint2* Bs)
{
    constexpr int ASN = 64 * 12;
    constexpr int BSN = TRANS_B ? 128 * 12 : 8 * 132;

    int t = threadIdx.x, warp = t >> 5, lane = t & 31;
    int g = lane >> 2, l3 = lane & 3;
    int wm = (warp & 1) * 32, wn = (warp >> 1) * 32;

    float acc[2][4][4] = {};

    int ar = t >> 2, akf = (t & 3) * 4, akp = (t & 3) * 2;
    int btr = t >> 1, btp = (t & 1) * 4;
    int bk = t >> 5, bn = (t & 31) * 4;

    int kt = GUARD ? ((K + 15) >> 4) : (K >> 4);
    uint4 ua, ub0, ub1;

    auto loadA = [&](int k0) {
        int gm = m0 + ar;
        if (AMODE == 2) {
            ua = make_uint4(0u, 0u, 0u, 0u);
            if (gm < M) ua = *(const uint4*)(Ah + (ll)gm * (lda >> 1) + (k0 >> 1) + akp);
        } else {
            float4 rv = make_float4(0.f, 0.f, 0.f, 0.f);
            if (gm < M) {
                int gk = k0 + akf;
                if (!GUARD || gk + 3 < K) {
                    rv = *(const float4*)(Af + (ll)gm * lda + gk);
                    if (AMODE == 3) {
                        float4 r2 = *(const float4*)(Af2 + (ll)gm * lda + gk);
                        rv.x += r2.x; rv.y += r2.y; rv.z += r2.z; rv.w += r2.w;
                    }
                } else {
                    const float* bp = Af + (ll)gm * lda;
                    rv.x = (gk     < K) ? bp[gk]     : 0.f;
                    rv.y = (gk + 1 < K) ? bp[gk + 1] : 0.f;
                    rv.z = (gk + 2 < K) ? bp[gk + 2] : 0.f;
                    rv.w = (gk + 3 < K) ? bp[gk + 3] : 0.f;
                }
                if (AMODE == 1) {
                    rv.x = fmaxf(rv.x, 0.f); rv.y = fmaxf(rv.y, 0.f);
                    rv.z = fmaxf(rv.z, 0.f); rv.w = fmaxf(rv.w, 0.f);
                }
            }
            uint2 p0 = cvt_pair(rv.x, rv.y), p1 = cvt_pair(rv.z, rv.w);
            ua = make_uint4(p0.x, p0.y, p1.x, p1.y);
        }
    };
    auto loadB = [&](int k0) {
        if (TRANS_B) {
            int gn = n0 + btr;
            ub0 = make_uint4(0u, 0u, 0u, 0u); ub1 = ub0;
            if (gn < N) {
                const uint2* p = Bh + (ll)gn * (K >> 1) + (k0 >> 1) + btp;
                ub0 = *(const uint4*)p;
                ub1 = *(const uint4*)(p + 2);
            }
        } else if (BMODE == 0) {
            const uint2* p = Bh + (ll)((k0 >> 1) + bk) * N + bn;
            ub0 = *(const uint4*)p;
            ub1 = *(const uint4*)(p + 2);
        } else {
            int gk0 = k0 + 2 * bk, gk1 = gk0 + 1;
            float4 r0 = make_float4(0.f, 0.f, 0.f, 0.f), r1 = r0;
            if (!GUARD || gk0 < K) r0 = *(const float4*)(Bf + (ll)gk0 * ldb + bn);
            if (!GUARD || gk1 < K) r1 = *(const float4*)(Bf + (ll)gk1 * ldb + bn);
            uint2 q0 = cvt_pair(r0.x, r1.x), q1 = cvt_pair(r0.y, r1.y);
            uint2 q2 = cvt_pair(r0.z, r1.z), q3 = cvt_pair(r0.w, r1.w);
            ub0 = make_uint4(q0.x, q0.y, q1.x, q1.y);
            ub1 = make_uint4(q2.x, q2.y, q3.x, q3.y);
        }
    };
    auto storeA = [&](int s) { *(uint4*)&As[s * ASN + ar * 12 + akp] = ua; };
    auto storeB = [&](int s) {
        if (TRANS_B) {
            *(uint4*)&Bs[s * BSN + btr * 12 + btp]     = ub0;
            *(uint4*)&Bs[s * BSN + btr * 12 + btp + 2] = ub1;
        } else {
            *(uint4*)&Bs[s * BSN + bk * 132 + bn]     = ub0;
            *(uint4*)&Bs[s * BSN + bk * 132 + bn + 2] = ub1;
        }
    };

    loadA(0); loadB(0);
    storeA(0); storeB(0);
    __syncthreads();

    for (int it = 0; it < kt; it++) {
        int s = it & 1;
        if (it + 1 < kt) { loadA((it + 1) << 4); loadB((it + 1) << 4); }

        uint32_t ahi[2][4], alo[2][4];
        #pragma unroll
        for (int mi = 0; mi < 2; mi++) {
            int rr = wm + mi * 16 + g;
            uint2 x0 = As[s * ASN + rr * 12 + l3];
            uint2 x1 = As[s * ASN + (rr + 8) * 12 + l3];
            uint2 x2 = As[s * ASN + rr * 12 + l3 + 4];
            uint2 x3 = As[s * ASN + (rr + 8) * 12 + l3 + 4];
            ahi[mi][0] = x0.x; alo[mi][0] = x0.y;
            ahi[mi][1] = x1.x; alo[mi][1] = x1.y;
            ahi[mi][2] = x2.x; alo[mi][2] = x2.y;
            ahi[mi][3] = x3.x; alo[mi][3] = x3.y;
        }
        uint32_t bhi[4][2], blo[4][2];
        #pragma unroll
        for (int ni = 0; ni < 4; ni++) {
            int cc = wn + ni * 8 + g;
            uint2 y0 = TRANS_B ? Bs[s * BSN + cc * 12 + l3]
                               : Bs[s * BSN + l3 * 132 + cc];
            uint2 y1 = TRANS_B ? Bs[s * BSN + cc * 12 + l3 + 4]
                               : Bs[s * BSN + (l3 + 4) * 132 + cc];
            bhi[ni][0] = y0.x; blo[ni][0] = y0.y;
            bhi[ni][1] = y1.x; blo[ni][1] = y1.y;
        }
        #pragma unroll
        for (int mi = 0; mi < 2; mi++)
            #pragma unroll
            for (int ni = 0; ni < 4; ni++) {
                mma_bf16(acc[mi][ni], ahi[mi], bhi[ni]);
                mma_bf16(acc[mi][ni], ahi[mi], blo[ni]);
                mma_bf16(acc[mi][ni], alo[mi], bhi[ni]);
            }
        if (it + 1 < kt) { storeA(s ^ 1); storeB(s ^ 1); }
        __syncthreads();
    }

    #pragma unroll
    for (int mi = 0; mi < 2; mi++)
        #pragma unroll
        for (int ni = 0; ni < 4; ni++) {
            int r0 = m0 + wm + mi * 16 + g;
            int c0 = n0 + wn + ni * 8 + 2 * l3;
            if (c0 >= N) continue;
            float b0 = 0.f, b1 = 0.f;
            if (bias) { b0 = bias[c0]; b1 = bias[c0 + 1]; }
            float v00 = (acc[mi][ni][0] + b0) * alpha;
            float v01 = (acc[mi][ni][1] + b1) * alpha;
            float v10 = (acc[mi][ni][2] + b0) * alpha;
            float v11 = (acc[mi][ni][3] + b1) * alpha;
            if (EPI == 0) {
                if (r0 < M)     *(float2*)(Cf + (ll)r0 * N + c0)       = make_float2(v00, v01);
                if (r0 + 8 < M) *(float2*)(Cf + (ll)(r0 + 8) * N + c0) = make_float2(v10, v11);
            } else {
                if (r0 < M)     Ch[(ll)r0 * (N >> 1) + (c0 >> 1)]       = cvt_pair(v00, v01);
                if (r0 + 8 < M) Ch[(ll)(r0 + 8) * (N >> 1) + (c0 >> 1)] = cvt_pair(v10, v11);
            }
        }
}

// ---------------- flash attention: fused QK^T + softmax + AV -----------------
// grid (16 q-tiles, B_), block 128 (4 warps x 16 q-rows). KV chunk = 32.
__global__ void __launch_bounds__(128)
flash_attn(const uint2* __restrict__ Qhl, const uint2* __restrict__ Khl,
           const float* __restrict__ Vf, float* __restrict__ AV)
{
    __shared__ __align__(16) uint2 Ks[32 * 68];   // [kv][dp] pitch 68
    __shared__ __align__(16) uint2 Vs[16 * 132];  // [kvp][d] pitch 132

    int b = blockIdx.y, m0 = blockIdx.x * 64;
    int t = threadIdx.x, w = t >> 5, lane = t & 31;
    int g = lane >> 2, l3 = lane & 3;
    int r0 = m0 + w * 16 + g, r1 = r0 + 8;

    // ---- Q fragments (held in registers for the whole kernel) ----
    uint32_t qhi[8][4], qlo[8][4];
    {
        const uint2* Q0 = Qhl + ((ll)b * LP_ + r0) * 64;
        const uint2* Q1 = Qhl + ((ll)b * LP_ + r1) * 64;
        #pragma unroll
        for (int s = 0; s < 8; s++) {
            uint2 u0 = make_uint2(0u,0u), u2 = u0, u1 = u0, u3 = u0;
            if (r0 < LP_) { u0 = Q0[8*s + l3]; u2 = Q0[8*s + l3 + 4]; }
            if (r1 < LP_) { u1 = Q1[8*s + l3]; u3 = Q1[8*s + l3 + 4]; }
            qhi[s][0] = u0.x; qlo[s][0] = u0.y;
            qhi[s][1] = u1.x; qlo[s][1] = u1.y;
            qhi[s][2] = u2.x; qlo[s][2] = u2.y;
            qhi[s][3] = u3.x; qlo[s][3] = u3.y;
        }
    }

    float accO[16][4] = {};
    float m0_ = -1e30f, m1_ = -1e30f, l0_ = 0.f, l1_ = 0.f;

    int kvp = t >> 3, dseg = (t & 7) * 16;   // V loader indices

    for (int iter = 0; iter < 32; iter++) {
        int kb = iter * 32;
        // ---- prefetch K chunk (32 rows x 32 uint4 = 1024 stores; j=0..7) ----
        uint4 kreg[8];
        #pragma unroll
        for (int j = 0; j < 8; j++) {
            int idx = t + 128 * j, row = idx >> 5, q4 = idx & 31;
            int gkv = kb + row;
            kreg[j] = (gkv < LP_)
                ? *(const uint4*)(Khl + ((ll)b * LP_ + gkv) * 64 + q4 * 2)
                : make_uint4(0u,0u,0u,0u);
        }
        float4 fA[4], fB[4];
        {
            int rA = kb + 2 * kvp, rB = rA + 1;
            #pragma unroll
            for (int dd = 0; dd < 4; dd++) {
                fA[dd] = (rA < LP_) ? *(const float4*)(Vf + ((ll)b * LP_ + rA) * 128 + dseg + 4*dd)
                                    : make_float4(0.f,0.f,0.f,0.f);
                fB[dd] = (rB < LP_) ? *(const float4*)(Vf + ((ll)b * LP_ + rB) * 128 + dseg + 4*dd)
                                    : make_float4(0.f,0.f,0.f,0.f);
            }
        }
        __syncthreads();   // previous iteration's MMA reads complete
        #pragma unroll
        for (int j = 0; j < 8; j++) {
            int idx = t + 128 * j, row = idx >> 5, q4 = idx & 31;
            *(uint4*)&Ks[row * 68 + q4 * 2] = kreg[j];
        }
        #pragma unroll
        for (int dd = 0; dd < 4; dd++) {
            uint2 p0 = cvt_pair(fA[dd].x, fB[dd].x);
            uint2 p1 = cvt_pair(fA[dd].y, fB[dd].y);
            uint2 p2 = cvt_pair(fA[dd].z, fB[dd].z);
            uint2 p3 = cvt_pair(fA[dd].w, fB[dd].w);
            uint2* vp = &Vs[kvp * 132 + dseg + 4*dd];
            *(uint4*)vp       = make_uint4(p0.x, p0.y, p1.x, p1.y);
            *(uint4*)(vp + 2) = make_uint4(p2.x, p2.y, p3.x, p3.y);
        }
        __syncthreads();

        // ---- S = Q @ K_chunk^T  (4 n-tiles of 8 kv) ----
        float sacc[4][4] = {};
        #pragma unroll
        for (int nt = 0; nt < 4; nt++) {
            int krow = nt * 8 + g;
            #pragma unroll
            for (int s = 0; s < 8; s++) {
                uint2 y0 = Ks[krow * 68 + 8*s + l3];
                uint2 y1 = Ks[krow * 68 + 8*s + l3 + 4];
                uint32_t bh[2] = {y0.x, y1.x}, bl[2] = {y0.y, y1.y};
                mma_bf16(sacc[nt], qhi[s], bh);
                mma_bf16(sacc[nt], qhi[s], bl);
                mma_bf16(sacc[nt], qlo[s], bh);
            }
        }

        // ---- online softmax ----
        float cm0 = -1e30f, cm1 = -1e30f;
        #pragma unroll
        for (int nt = 0; nt < 4; nt++) {
            cm0 = fmaxf(cm0, fmaxf(sacc[nt][0], sacc[nt][1]));
            cm1 = fmaxf(cm1, fmaxf(sacc[nt][2], sacc[nt][3]));
        }
        cm0 = fmaxf(cm0, __shfl_xor_sync(0xffffffffu, cm0, 1));
        cm0 = fmaxf(cm0, __shfl_xor_sync(0xffffffffu, cm0, 2));
        cm1 = fmaxf(cm1, __shfl_xor_sync(0xffffffffu, cm1, 1));
        cm1 = fmaxf(cm1, __shfl_xor_sync(0xffffffffu, cm1, 2));
        float mn0 = fmaxf(m0_, cm0), mn1 = fmaxf(m1_, cm1);
        float sc0 = __expf(m0_ - mn0), sc1 = __expf(m1_ - mn1);
        m0_ = mn0; m1_ = mn1;

        uint32_t phi[2][4], plo[2][4];
        float rs0 = 0.f, rs1 = 0.f;
        #pragma unroll
        for (int nt = 0; nt < 4; nt++) {
            int c0 = kb + nt * 8 + 2 * l3;
            bool v0 = c0 < LP_, v1 = (c0 + 1) < LP_;
            float p00 = v0 ? __expf(sacc[nt][0] - mn0) : 0.f;
            float p01 = v1 ? __expf(sacc[nt][1] - mn0) : 0.f;
            float p10 = v0 ? __expf(sacc[nt][2] - mn1) : 0.f;
            float p11 = v1 ? __expf(sacc[nt][3] - mn1) : 0.f;
            rs0 += p00 + p01; rs1 += p10 + p11;
            uint2 hA = cvt_pair(p00, p01);
            uint2 hB = cvt_pair(p10, p11);
            int s2 = nt >> 1, o = (nt & 1) * 2;
            phi[s2][o]     = hA.x; plo[s2][o]     = hA.y;
            phi[s2][o + 1] = hB.x; plo[s2][o + 1] = hB.y;
        }
        rs0 += __shfl_xor_sync(0xffffffffu, rs0, 1);
        rs0 += __shfl_xor_sync(0xffffffffu, rs0, 2);
        rs1 += __shfl_xor_sync(0xffffffffu, rs1, 1);
        rs1 += __shfl_xor_sync(0xffffffffu, rs1, 2);
        l0_ = l0_ * sc0 + rs0;
        l1_ = l1_ * sc1 + rs1;
        #pragma unroll
        for (int dt = 0; dt < 16; dt++) {
            accO[dt][0] *= sc0; accO[dt][1] *= sc0;
            accO[dt][2] *= sc1; accO[dt][3] *= sc1;
        }

        // ---- O += P @ V_chunk ----
        #pragma unroll
        for (int dt = 0; dt < 16; dt++) {
            #pragma unroll
            for (int s2 = 0; s2 < 2; s2++) {
                int vr = 8 * s2 + l3;
                uint2 y0 = Vs[vr * 132 + dt * 8 + g];
                uint2 y1 = Vs[(vr + 4) * 132 + dt * 8 + g];
                uint32_t bh[2] = {y0.x, y1.x}, bl[2] = {y0.y, y1.y};
                mma_bf16(accO[dt], phi[s2], bh);
                mma_bf16(accO[dt], phi[s2], bl);
                mma_bf16(accO[dt], plo[s2], bh);
            }
        }
    }

    // ---- finalize: divide by l, write AV ----
    float inv0 = 1.f / l0_, inv1 = 1.f / l1_;
    #pragma unroll
    for (int dt = 0; dt < 16; dt++) {
        int c = dt * 8 + 2 * l3;
        if (r0 < LP_)
            *(float2*)(AV + ((ll)b * LP_ + r0) * 128 + c) =
                make_float2(accO[dt][0] * inv0, accO[dt][1] * inv0);
        if (r1 < LP_)
            *(float2*)(AV + ((ll)b * LP_ + r1) * 128 + c) =
                make_float2(accO[dt][2] * inv1, accO[dt][3] * inv1);
    }
}

// ---------------- wrappers ----------------------------------------------------
__global__ void repack_kernel(const float* __restrict__ W, uint2* __restrict__ O,
                              int N, int total)
{
    int i = blockIdx.x * 256 + threadIdx.x;
    if (i >= total) return;
    int kp = i / N, n = i - kp * N;
    O[i] = cvt_pair(W[(ll)(2 * kp) * N + n], W[(ll)(2 * kp + 1) * N + n]);
}
// 6 weight repacks + fuse_bq merged (y==6)
__global__ void prep6_kernel(const float* w0, const float* w1, const float* w2,
                             const float* w3, const float* w4, const float* w5,
                             uint2* d0, uint2* d1, uint2* d2,
                             uint2* d3, uint2* d4, uint2* d5,
                             const float* emb_b, const float* wq_b, float* bq)
{
    if (blockIdx.y == 6) {
        if (blockIdx.x == 0 && threadIdx.x < 128) {
            int n = threadIdx.x;
            float s = wq_b[n];
            for (int k = 0; k < D_; k++) s = fmaf(emb_b[k], w0[k * D_ + n], s);
            bq[n] = s;
        }
        return;
    }
    int i = blockIdx.x * 256 + threadIdx.x;
    const float* s; uint2* d;
    switch (blockIdx.y) {
        case 0: s = w0; d = d0; break;
        case 1: s = w1; d = d1; break;
        case 2: s = w2; d = d2; break;
        case 3: s = w3; d = d3; break;
        case 4: s = w4; d = d4; break;
        default: s = w5; d = d5; break;
    }
    int kp = i >> 7, n = i & 127;
    d[i] = cvt_pair(s[(2 * kp) * D_ + n], s[(2 * kp + 1) * D_ + n]);
}

__global__ void __launch_bounds__(256, 2)
gemm_wqp(const float* __restrict__ emb_w, const uint2* __restrict__ wqp,
         float* __restrict__ Wq0)
{
    __shared__ __align__(16) uint2 As[2 * 64 * 12];
    __shared__ __align__(16) uint2 Bs[2 * 8 * 132];
    gemm_body<0, 0, false, 0, false>(emb_w, nullptr, nullptr, wqp, nullptr,
        nullptr, Wq0, nullptr, E_, D_, D_, D_, D_, 1.f, blockIdx.y * 64, 0, As, Bs);
}

__global__ void __launch_bounds__(256, 2)
gemm_qkv(const float* __restrict__ in_pe, const uint2* __restrict__ Wqp,
         const float* __restrict__ bq, uint2* __restrict__ Qhl,
         const float* __restrict__ in_pfx,
         const uint2* __restrict__ wkp, const float* __restrict__ wk_b,
         uint2* __restrict__ Khl,
         const uint2* __restrict__ wvp, const float* __restrict__ wv_b,
         float* __restrict__ Vf, float inv_sqrt_d)
{
    __shared__ __align__(16) uint2 As[2 * 64 * 12];
    __shared__ __align__(16) uint2 Bs[2 * 8 * 132];
    int m0 = blockIdx.y * 64;
    if (blockIdx.z == 0)
        gemm_body<0, 0, false, 1, false>(in_pe, nullptr, nullptr, Wqp, nullptr,
            bq, nullptr, Qhl, B_*LP_, D_, E_, E_, D_, inv_sqrt_d, m0, 0, As, Bs);
    else if (blockIdx.z == 1)
        gemm_body<0, 0, false, 1, false>(in_pfx, nullptr, nullptr, wkp, nullptr,
            wk_b, nullptr, Khl, B_*LP_, D_, D_, D_, D_, 1.f, m0, 0, As, Bs);
    else
        gemm_body<0, 0, false, 0, false>(in_pfx, nullptr, nullptr, wvp, nullptr,
            wv_b, Vf, nullptr, B_*LP_, D_, D_, D_, D_, 1.f, m0, 0, As, Bs);
}

__global__ void __launch_bounds__(256, 2)
gemm_wo(const float* __restrict__ AV,
        const uint2* __restrict__ wop, const float* __restrict__ wo_b,
        float* __restrict__ pf)
{
    __shared__ __align__(16) uint2 As[2 * 64 * 12];
    __shared__ __align__(16) uint2 Bs[2 * 8 * 132];
    gemm_body<0, 0, false, 0, false>(AV, nullptr, nullptr, wop, nullptr,
        wo_b, pf, nullptr, B_*LP_, D_, D_, D_, D_, 1.f, blockIdx.y * 64, 0, As, Bs);
}

__global__ void __launch_bounds__(256, 2)
gemm_pc(const float* __restrict__ pf, const uint2* __restrict__ jpp,
        const float* __restrict__ jp_b, float* __restrict__ P,
        const float* __restrict__ cf, const uint2* __restrict__ jcp,
        const float* __restrict__ jc_b, uint2* __restrict__ Chl)
{
    if (blockIdx.z == 1 && blockIdx.y >= 8) return;
    __shared__ __align__(16) uint2 As[2 * 64 * 12];
    __shared__ __align__(16) uint2 Bs[2 * 8 * 132];
    int m0 = blockIdx.y * 64;
    if (blockIdx.z == 0)
        gemm_body<1, 0, false, 0, false>(pf, nullptr, nullptr, jpp, nullptr,
            jp_b, P, nullptr, B_*LP_, D_, D_, D_, D_, 1.f, m0, 0, As, Bs);
    else
        gemm_body<1, 0, false, 1, false>(cf, nullptr, nullptr, jcp, nullptr,
            jc_b, nullptr, Chl, B_*NC_, D_, D_, D_, D_, 1.f, m0, 0, As, Bs);
}

// ---------------- A-logits: bf16x3 64x64 GEMM + sigmoid + partial sums -------
__global__ void __launch_bounds__(256, 2)
alogits_kernel(const float* __restrict__ Pm, const uint2* __restrict__ Chl,
               float* __restrict__ Aout, float* __restrict__ Apart)
{
    __shared__ __align__(16) uint2 As[2][768];
    __shared__ __align__(16) uint2 Bs[2][768];
    __shared__ float red[256];

    int b = blockIdx.y, mt = blockIdx.x, m0 = mt * 64;
    const float* A = Pm + (ll)b * LP_ * D_;
    const uint2* Bh = Chl + (ll)b * NC_ * 64;
    float* C = Aout + (ll)b * LP_ * NC_;
    int t = threadIdx.x, warp = t >> 5, lane = t & 31;
    int g = lane >> 2, l3 = lane & 3;
    int wm = (warp & 1) * 32, wn = (warp >> 1) * 16;

    float acc[2][2][4] = {};
    int ar = t >> 2, akf = (t & 3) * 4, akp = (t & 3) * 2;
    uint4 ua, ub;

    auto loadAB = [&](int k0) {
        int gm = m0 + ar;
        float4 rv = make_float4(0.f, 0.f, 0.f, 0.f);
        if (gm < LP_) rv = *(const float4*)(A + (ll)gm * D_ + k0 + akf);
        uint2 p0 = cvt_pair(rv.x, rv.y), p1 = cvt_pair(rv.z, rv.w);
        ua = make_uint4(p0.x, p0.y, p1.x, p1.y);
        ub = *(const uint4*)(Bh + (ll)ar * 64 + (k0 >> 1) + akp);
    };
    auto storeAB = [&](int s) {
        *(uint4*)&As[s][ar * 12 + akp] = ua;
        *(uint4*)&Bs[s][ar * 12 + akp] = ub;
    };
    loadAB(0); storeAB(0);
    __syncthreads();

    for (int it = 0; it < 8; it++) {
        int s = it & 1;
        if (it < 7) loadAB((it + 1) << 4);
        uint32_t ahi[2][4], alo[2][4];
        #pragma unroll
        for (int mi = 0; mi < 2; mi++) {
            int rr = wm + mi * 16 + g;
            uint2 x0 = As[s][rr * 12 + l3];
            uint2 x1 = As[s][(rr + 8) * 12 + l3];
            uint2 x2 = As[s][rr * 12 + l3 + 4];
            uint2 x3 = As[s][(rr + 8) * 12 + l3 + 4];
            ahi[mi][0] = x0.x; alo[mi][0] = x0.y;
            ahi[mi][1] = x1.x; alo[mi][1] = x1.y;
            ahi[mi][2] = x2.x; alo[mi][2] = x2.y;
            ahi[mi][3] = x3.x; alo[mi][3] = x3.y;
        }
        uint32_t bhi[2][2], blo[2][2];
        #pragma unroll
        for (int ni = 0; ni < 2; ni++) {
            int cc = wn + ni * 8 + g;
            uint2 y0 = Bs[s][cc * 12 + l3];
            uint2 y1 = Bs[s][cc * 12 + l3 + 4];
            bhi[ni][0] = y0.x; blo[ni][0] = y0.y;
            bhi[ni][1] = y1.x; blo[ni][1] = y1.y;
        }
        #pragma unroll
        for (int mi = 0; mi < 2; mi++)
            #pragma unroll
            for (int ni = 0; ni < 2; ni++) {
                mma_bf16(acc[mi][ni], ahi[mi], bhi[ni]);
                mma_bf16(acc[mi][ni], ahi[mi], blo[ni]);
                mma_bf16(acc[mi][ni], alo[mi], bhi[ni]);
            }
        if (it < 7) storeAB(s ^ 1);
        __syncthreads();
    }

    float tsum = 0.f;
    #pragma unroll
    for (int mi = 0; mi < 2; mi++)
        #pragma unroll
        for (int ni = 0; ni < 2; ni++) {
            int r0 = m0 + wm + mi * 16 + g;
            int c0 = wn + ni * 8 + 2 * l3;
            if (r0 < LP_) {
                float v0 = 1.f / (1.f + __expf(-acc[mi][ni][0]));
                float v1 = 1.f / (1.f + __expf(-acc[mi][ni][1]));
                *(float2*)(C + (ll)r0 * NC_ + c0) = make_float2(v0, v1);
                tsum += v0 + v1;
            }
            if (r0 + 8 < LP_) {
                float v0 = 1.f / (1.f + __expf(-acc[mi][ni][2]));
                float v1 = 1.f / (1.f + __expf(-acc[mi][ni][3]));
                *(float2*)(C + (ll)(r0 + 8) * NC_ + c0) = make_float2(v0, v1);
                tsum += v0 + v1;
            }
        }
    red[t] = tsum; __syncthreads();
    for (int s2 = 128; s2 > 0; s2 >>= 1) {
        if (t < s2) red[t] += red[t + s2];
        __syncthreads();
    }
    if (t == 0) Apart[b * 16 + mt] = red[0];
}

// ---------------- tanh outer-product weighted reduction ---------------------
__global__ void tanh_outer_kernel(const float* __restrict__ pf,
                                  const float* __restrict__ cf,
                                  const float* __restrict__ A,
                                  float* __restrict__ part)
{
    int b = blockIdx.y, tile = blockIdx.x;
    int d = threadIdx.x;  // 128
    __shared__ float cfs[NC_ * D_];
    for (int i = threadIdx.x; i < NC_ * D_; i += 128)
        cfs[i] = cf[(ll)b * NC_ * D_ + i];
    __syncthreads();
    float acc = 0.f;
    int i0 = tile * ITILE_;
    for (int i = i0; i < i0 + ITILE_; i++) {
        float pv = pf[((ll)b * LP_ + i) * D_ + d];
        const float* Ar = A + ((ll)b * LP_ + i) * NC_;
        #pragma unroll 4
        for (int k = 0; k < NC_; k++) {
            float w = Ar[k];
            float x = pv * cfs[k * D_ + d];
            float th;
            asm("tanh.approx.f32 %0, %1;" : "=f"(th) : "f"(x));
            acc = fmaf(th, w, acc);
        }
    }
    part[((ll)b * NTILE_ + tile) * D_ + d] = acc;
}

__global__ void cp_reduce_kernel(const float* __restrict__ part,
                                 const float* __restrict__ Apart,
                                 float* __restrict__ cp)
{
    int b = blockIdx.x;
    int d = threadIdx.x;  // 128
    float as = 0.f;
    #pragma unroll
    for (int j = 0; j < 16; j++) as += Apart[b * 16 + j];
    float s = 0.f;
    for (int t2 = 0; t2 < NTILE_; t2++)
        s += part[((ll)b * NTILE_ + t2) * D_ + d];
    cp[b * D_ + d] = s / as;
}

// ---------------- skinny GEMM (M = 8 rows) -----------------------------------
template<bool RELU_OUT>
__global__ void __launch_bounds__(256)
skinny_gemm(const float* __restrict__ A, const float* __restrict__ W,
            const float* __restrict__ bias, float* __restrict__ C,
            int N, int K)
{
    __shared__ float As[8 * 1024];
    __shared__ float red[8][8][32];
    int t = threadIdx.x;
    for (int i = t; i < 8 * K; i += 256) As[i] = A[i];
    __syncthreads();
    int n = blockIdx.x * 32 + (t & 31);
    int ks = t >> 5;
    int kseg = K >> 3;
    float acc[8] = {};
    if (n < N) {
        for (int k = ks * kseg; k < (ks + 1) * kseg; k++) {
            float w = W[(ll)k * N + n];
            #pragma unroll
            for (int m = 0; m < 8; m++) acc[m] = fmaf(As[m * K + k], w, acc[m]);
        }
    }
    #pragma unroll
    for (int m = 0; m < 8; m++) red[ks][m][t & 31] = acc[m];
    __syncthreads();
    int m = t >> 5, lnn = t & 31;
    int nn = blockIdx.x * 32 + lnn;
    if (nn < N) {
        float s = 0.f;
        #pragma unroll
        for (int j = 0; j < 8; j++) s += red[j][m][lnn];
        s += bias[nn];
        if (RELU_OUT) s = fmaxf(s, 0.f);
        C[(ll)m * N + nn] = s;
    }
}

// ---------------- launch ------------------------------------------------------
extern "C" void kernel_launch(void* const* d_in, const int* in_sizes, int n_in,
                              void* d_out, int out_size)
{
    const float* in_pe  = (const float*)d_in[0];
    const float* in_pfx = (const float*)d_in[1];
    const float* in_cf  = (const float*)d_in[2];
    const float* emb_w = (const float*)d_in[3];  const float* emb_b = (const float*)d_in[4];
    const float* wq_w  = (const float*)d_in[5];  const float* wq_b  = (const float*)d_in[6];
    const float* wk_w  = (const float*)d_in[7];  const float* wk_b  = (const float*)d_in[8];
    const float* wv_w  = (const float*)d_in[9];  const float* wv_b  = (const float*)d_in[10];
    const float* wo_w  = (const float*)d_in[11]; const float* wo_b  = (const float*)d_in[12];
    const float* jp_w  = (const float*)d_in[13]; const float* jp_b  = (const float*)d_in[14];
    const float* jc_w  = (const float*)d_in[15]; const float* jc_b  = (const float*)d_in[16];
    const float* c1_w  = (const float*)d_in[17]; const float* c1_b  = (const float*)d_in[18];
    const float* c2_w  = (const float*)d_in[19]; const float* c2_b  = (const float*)d_in[20];
    const float* c3_w  = (const float*)d_in[21]; const float* c3_b  = (const float*)d_in[22];
    const float* c4_w  = (const float*)d_in[23]; const float* c4_b  = (const float*)d_in[24];

    uint2 *Qhl, *Khl, *Chl, *wqp, *wkp, *wvp, *wop, *jpp, *jcp, *Wqp;
    float *Wq0, *Vf, *AV, *pf, *P, *A, *bq, *Apart, *part, *cp, *h1, *h2, *h3;
    cudaGetSymbolAddress((void**)&Qhl,  g_Qhl);
    cudaGetSymbolAddress((void**)&Khl,  g_Khl);
    cudaGetSymbolAddress((void**)&Chl,  g_Chl);
    cudaGetSymbolAddress((void**)&wqp,  g_wqp);
    cudaGetSymbolAddress((void**)&wkp,  g_wkp);
    cudaGetSymbolAddress((void**)&wvp,  g_wvp);
    cudaGetSymbolAddress((void**)&wop,  g_wop);
    cudaGetSymbolAddress((void**)&jpp,  g_jpp);
    cudaGetSymbolAddress((void**)&jcp,  g_jcp);
    cudaGetSymbolAddress((void**)&Wqp,  g_Wqp);
    cudaGetSymbolAddress((void**)&Wq0,  g_Wq0);
    cudaGetSymbolAddress((void**)&Vf,   g_Vf);
    cudaGetSymbolAddress((void**)&AV,   g_AV);
    cudaGetSymbolAddress((void**)&pf,   g_pf);
    cudaGetSymbolAddress((void**)&P,    g_P);
    cudaGetSymbolAddress((void**)&A,    g_A);
    cudaGetSymbolAddress((void**)&bq,   g_bq);
    cudaGetSymbolAddress((void**)&Apart,g_Apart);
    cudaGetSymbolAddress((void**)&part, g_part);
    cudaGetSymbolAddress((void**)&cp,   g_cp);
    cudaGetSymbolAddress((void**)&h1,   g_h1);
    cudaGetSymbolAddress((void**)&h2,   g_h2);
    cudaGetSymbolAddress((void**)&h3,   g_h3);

    const float inv_sqrt_d = 0.088388347648318440550f;  // 1/sqrt(128)

    // 0. weights -> bf16 pairs (+ bq fused); Wq' = emb_w @ wq_w; repack
    prep6_kernel<<<dim3(32,7),256>>>(wq_w, wk_w, wv_w, wo_w, jp_w, jc_w,
                                     wqp, wkp, wvp, wop, jpp, jcp,
                                     emb_b, wq_b, bq);
    gemm_wqp<<<dim3(1,5),256>>>(emb_w, wqp, Wq0);
    repack_kernel<<<80,256>>>(Wq0, Wqp, D_, 160 * D_);
    // 1. Q/K/V (Q pre-scaled; Q,K as pairs, V fp32)
    gemm_qkv<<<dim3(1,125,3),256>>>(in_pe, Wqp, bq, Qhl,
                                    in_pfx, wkp, wk_b, Khl,
                                    wvp, wv_b, Vf, inv_sqrt_d);
    // 2. fused attention: AV = softmax(Qs K^T) V
    flash_attn<<<dim3(16,B_),128>>>(Qhl, Khl, Vf, AV);
    // 3. pf = AV @ wo + b
    gemm_wo<<<dim3(1,125),256>>>(AV, wop, wo_b, pf);
    // 4. P / Chl
    gemm_pc<<<dim3(1,125,2),256>>>(pf, jpp, jp_b, P, in_cf, jcp, jc_b, Chl);
    // 5. A = sigmoid(P @ C^T) + partial sums
    alogits_kernel<<<dim3(16,B_),256>>>(P, Chl, A, Apart);
    // 6. tanh outer product partials
    tanh_outer_kernel<<<dim3(NTILE_,B_),128>>>(pf, in_cf, A, part);
    // 7. reduce + normalize
    cp_reduce_kernel<<<B_,128>>>(part, Apart, cp);
    // 8-11. classifier MLP
    skinny_gemm<true ><<<32,256>>>(cp, c1_w, c1_b, h1, 1024, D_);
    skinny_gemm<true ><<<32,256>>>(h1, c2_w, c2_b, h2, 1024, 1024);
    skinny_gemm<true ><<<8, 256>>>(h2, c3_w, c3_b, h3, 256, 1024);
    skinny_gemm<false><<<1, 256>>>(h3, c4_w, c4_b, (float*)d_out, 1, 256);
}

// round 9
// speedup vs baseline: 1.6916x; 1.1257x over previous
#include <cuda_runtime.h>
#include <math.h>
#include <stdint.h>

#define B_  8
#define LP_ 1000
#define NC_ 64
#define D_  128
#define E_  320
#define NTILE_ 100
#define ITILE_ 10
typedef long long ll;

// ---------------- scratch (device globals) ----------------------------------
__device__ __align__(16) uint2 g_Qhl[B_*LP_*64];    // bf16 hi/lo pairs along d
__device__ __align__(16) uint2 g_Khl[B_*LP_*64];
__device__ __align__(16) uint2 g_Chl[B_*NC_*64];
__device__ __align__(16) uint2 g_wkp[64*D_];
__device__ __align__(16) uint2 g_wvp[64*D_];
__device__ __align__(16) uint2 g_wop[64*D_];
__device__ __align__(16) uint2 g_jpp[64*D_];
__device__ __align__(16) uint2 g_jcp[64*D_];
__device__ __align__(16) float g_Wq0[E_*D_];
__device__ __align__(16) float g_Vf [B_*LP_*D_];
__device__ __align__(16) float g_AV0[B_*LP_*D_];
__device__ __align__(16) float g_AV1[B_*LP_*D_];
__device__ __align__(16) float g_M0 [B_*LP_];
__device__ __align__(16) float g_L0 [B_*LP_];
__device__ __align__(16) float g_M1 [B_*LP_];
__device__ __align__(16) float g_L1 [B_*LP_];
__device__ __align__(16) float g_pf [B_*LP_*D_];
__device__ __align__(16) float g_P  [B_*LP_*D_];
__device__ __align__(16) float g_A  [B_*LP_*NC_];
__device__ __align__(16) float g_bq [D_];
__device__ __align__(16) float g_Apart[B_*16];
__device__ __align__(16) float g_part[B_*NTILE_*D_];
__device__ __align__(16) float g_cp [B_*D_];
__device__ __align__(16) float g_h1 [B_*1024];
__device__ __align__(16) float g_h2 [B_*1024];
__device__ __align__(16) float g_h3 [B_*256];

// ---------------- bf16 helpers -----------------------------------------------
__device__ __forceinline__ uint32_t packbf(float x, float y) {  // lo=x, hi=y
    uint32_t r;
    asm("cvt.rn.bf16x2.f32 %0, %1, %2;" : "=r"(r) : "f"(y), "f"(x));
    return r;
}
__device__ __forceinline__ float lowbf(uint32_t h)  { return __uint_as_float(h << 16); }
__device__ __forceinline__ float highbf(uint32_t h) { return __uint_as_float(h & 0xFFFF0000u); }
__device__ __forceinline__ uint2 cvt_pair(float x, float y) {
    uint32_t h = packbf(x, y);
    uint32_t l = packbf(x - lowbf(h), y - highbf(h));
    return make_uint2(h, l);
}
__device__ __forceinline__ void mma_bf16(float* d, const uint32_t* a, const uint32_t* b) {
    asm volatile(
        "mma.sync.aligned.m16n8k16.row.col.f32.bf16.bf16.f32 "
        "{%0,%1,%2,%3}, {%4,%5,%6,%7}, {%8,%9}, {%0,%1,%2,%3};\n"
        : "+f"(d[0]), "+f"(d[1]), "+f"(d[2]), "+f"(d[3])
        : "r"(a[0]), "r"(a[1]), "r"(a[2]), "r"(a[3]), "r"(b[0]), "r"(b[1]));
}

// ---------------- unified GEMM body: 64(M) x 128(N) tile, BK=16, bf16x3 -----
// AMODE: 0=A fp32 cvt, 1=fp32+relu, 2=A pre-paired uint2, 3=dual fp32 add,
//        4=flash-combine (Af,Af2 unnorm + M/L row stats)
// BMODE: 0=pre-paired, 1=fp32 nontrans pack-on-fly
// EPI: 0=fp32 out, 1=pair uint2 out.  GUARD: K-tail bounds.
template<int AMODE, int BMODE, bool TRANS_B, int EPI, bool GUARD>
__device__ __forceinline__ void gemm_body(
    const float* __restrict__ Af, const float* __restrict__ Af2,
    const float* __restrict__ M0p, const float* __restrict__ L0p,
    const float* __restrict__ M1p, const float* __restrict__ L1p,
    const uint2* __restrict__ Ah,
    const uint2* __restrict__ Bh, const float* __restrict__ Bf,
    const float* __restrict__ bias, float* __restrict__ Cf, uint2* __restrict__ Ch,
    int M, int N, int K, int lda, int ldb,
    float alpha, int m0, int n0, uint2* As, uint2* Bs)
{
    constexpr int ASN = 64 * 12;
    constexpr int BSN = TRANS_B ? 128 * 12 : 8 * 132;

    int t = threadIdx.x, warp = t >> 5, lane = t & 31;
    int g = lane >> 2, l3 = lane & 3;
    int wm = (warp & 1) * 32, wn = (warp >> 1) * 32;

    float acc[2][4][4] = {};

    int ar = t >> 2, akf = (t & 3) * 4, akp = (t & 3) * 2;
    int btr = t >> 1, btp = (t & 1) * 4;
    int bk = t >> 5, bn = (t & 31) * 4;

    int kt = GUARD ? ((K + 15) >> 4) : (K >> 4);
    uint4 ua, ub0, ub1;

    auto loadA = [&](int k0) {
        int gm = m0 + ar;
        if (AMODE == 2) {
            ua = make_uint4(0u, 0u, 0u, 0u);
            if (gm < M) ua = *(const uint4*)(Ah + (ll)gm * (lda >> 1) + (k0 >> 1) + akp);
        } else {
            float4 rv = make_float4(0.f, 0.f, 0.f, 0.f);
            if (gm < M) {
                int gk = k0 + akf;
                if (!GUARD || gk + 3 < K) {
                    rv = *(const float4*)(Af + (ll)gm * lda + gk);
                    if (AMODE == 3) {
                        float4 r2 = *(const float4*)(Af2 + (ll)gm * lda + gk);
                        rv.x += r2.x; rv.y += r2.y; rv.z += r2.z; rv.w += r2.w;
                    }
                    if (AMODE == 4) {
                        float4 r2 = *(const float4*)(Af2 + (ll)gm * lda + gk);
                        float m0v = M0p[gm], m1v = M1p[gm];
                        float mm = fmaxf(m0v, m1v);
                        float a0 = __expf(m0v - mm), a1 = __expf(m1v - mm);
                        float inv = 1.f / (a0 * L0p[gm] + a1 * L1p[gm]);
                        rv.x = (rv.x * a0 + r2.x * a1) * inv;
                        rv.y = (rv.y * a0 + r2.y * a1) * inv;
                        rv.z = (rv.z * a0 + r2.z * a1) * inv;
                        rv.w = (rv.w * a0 + r2.w * a1) * inv;
                    }
                } else {
                    const float* bp = Af + (ll)gm * lda;
                    rv.x = (gk     < K) ? bp[gk]     : 0.f;
                    rv.y = (gk + 1 < K) ? bp[gk + 1] : 0.f;
                    rv.z = (gk + 2 < K) ? bp[gk + 2] : 0.f;
                    rv.w = (gk + 3 < K) ? bp[gk + 3] : 0.f;
                }
                if (AMODE == 1) {
                    rv.x = fmaxf(rv.x, 0.f); rv.y = fmaxf(rv.y, 0.f);
                    rv.z = fmaxf(rv.z, 0.f); rv.w = fmaxf(rv.w, 0.f);
                }
            }
            uint2 p0 = cvt_pair(rv.x, rv.y), p1 = cvt_pair(rv.z, rv.w);
            ua = make_uint4(p0.x, p0.y, p1.x, p1.y);
        }
    };
    auto loadB = [&](int k0) {
        if (TRANS_B) {
            int gn = n0 + btr;
            ub0 = make_uint4(0u, 0u, 0u, 0u); ub1 = ub0;
            if (gn < N) {
                const uint2* p = Bh + (ll)gn * (K >> 1) + (k0 >> 1) + btp;
                ub0 = *(const uint4*)p;
                ub1 = *(const uint4*)(p + 2);
            }
        } else if (BMODE == 0) {
            const uint2* p = Bh + (ll)((k0 >> 1) + bk) * N + bn;
            ub0 = *(const uint4*)p;
            ub1 = *(const uint4*)(p + 2);
        } else {
            int gk0 = k0 + 2 * bk, gk1 = gk0 + 1;
            float4 r0 = make_float4(0.f, 0.f, 0.f, 0.f), r1 = r0;
            if (!GUARD || gk0 < K) r0 = *(const float4*)(Bf + (ll)gk0 * ldb + bn);
            if (!GUARD || gk1 < K) r1 = *(const float4*)(Bf + (ll)gk1 * ldb + bn);
            uint2 q0 = cvt_pair(r0.x, r1.x), q1 = cvt_pair(r0.y, r1.y);
            uint2 q2 = cvt_pair(r0.z, r1.z), q3 = cvt_pair(r0.w, r1.w);
            ub0 = make_uint4(q0.x, q0.y, q1.x, q1.y);
            ub1 = make_uint4(q2.x, q2.y, q3.x, q3.y);
        }
    };
    auto storeA = [&](int s) { *(uint4*)&As[s * ASN + ar * 12 + akp] = ua; };
    auto storeB = [&](int s) {
        if (TRANS_B) {
            *(uint4*)&Bs[s * BSN + btr * 12 + btp]     = ub0;
            *(uint4*)&Bs[s * BSN + btr * 12 + btp + 2] = ub1;
        } else {
            *(uint4*)&Bs[s * BSN + bk * 132 + bn]     = ub0;
            *(uint4*)&Bs[s * BSN + bk * 132 + bn + 2] = ub1;
        }
    };

    loadA(0); loadB(0);
    storeA(0); storeB(0);
    __syncthreads();

    for (int it = 0; it < kt; it++) {
        int s = it & 1;
        if (it + 1 < kt) { loadA((it + 1) << 4); loadB((it + 1) << 4); }

        uint32_t ahi[2][4], alo[2][4];
        #pragma unroll
        for (int mi = 0; mi < 2; mi++) {
            int rr = wm + mi * 16 + g;
            uint2 x0 = As[s * ASN + rr * 12 + l3];
            uint2 x1 = As[s * ASN + (rr + 8) * 12 + l3];
            uint2 x2 = As[s * ASN + rr * 12 + l3 + 4];
            uint2 x3 = As[s * ASN + (rr + 8) * 12 + l3 + 4];
            ahi[mi][0] = x0.x; alo[mi][0] = x0.y;
            ahi[mi][1] = x1.x; alo[mi][1] = x1.y;
            ahi[mi][2] = x2.x; alo[mi][2] = x2.y;
            ahi[mi][3] = x3.x; alo[mi][3] = x3.y;
        }
        uint32_t bhi[4][2], blo[4][2];
        #pragma unroll
        for (int ni = 0; ni < 4; ni++) {
            int cc = wn + ni * 8 + g;
            uint2 y0 = TRANS_B ? Bs[s * BSN + cc * 12 + l3]
                               : Bs[s * BSN + l3 * 132 + cc];
            uint2 y1 = TRANS_B ? Bs[s * BSN + cc * 12 + l3 + 4]
                               : Bs[s * BSN + (l3 + 4) * 132 + cc];
            bhi[ni][0] = y0.x; blo[ni][0] = y0.y;
            bhi[ni][1] = y1.x; blo[ni][1] = y1.y;
        }
        #pragma unroll
        for (int mi = 0; mi < 2; mi++)
            #pragma unroll
            for (int ni = 0; ni < 4; ni++) {
                mma_bf16(acc[mi][ni], ahi[mi], bhi[ni]);
                mma_bf16(acc[mi][ni], ahi[mi], blo[ni]);
                mma_bf16(acc[mi][ni], alo[mi], bhi[ni]);
            }
        if (it + 1 < kt) { storeA(s ^ 1); storeB(s ^ 1); }
        __syncthreads();
    }

    #pragma unroll
    for (int mi = 0; mi < 2; mi++)
        #pragma unroll
        for (int ni = 0; ni < 4; ni++) {
            int r0 = m0 + wm + mi * 16 + g;
            int c0 = n0 + wn + ni * 8 + 2 * l3;
            if (c0 >= N) continue;
            float b0 = 0.f, b1 = 0.f;
            if (bias) { b0 = bias[c0]; b1 = bias[c0 + 1]; }
            float v00 = (acc[mi][ni][0] + b0) * alpha;
            float v01 = (acc[mi][ni][1] + b1) * alpha;
            float v10 = (acc[mi][ni][2] + b0) * alpha;
            float v11 = (acc[mi][ni][3] + b1) * alpha;
            if (EPI == 0) {
                if (r0 < M)     *(float2*)(Cf + (ll)r0 * N + c0)       = make_float2(v00, v01);
                if (r0 + 8 < M) *(float2*)(Cf + (ll)(r0 + 8) * N + c0) = make_float2(v10, v11);
            } else {
                if (r0 < M)     Ch[(ll)r0 * (N >> 1) + (c0 >> 1)]       = cvt_pair(v00, v01);
                if (r0 + 8 < M) Ch[(ll)(r0 + 8) * (N >> 1) + (c0 >> 1)] = cvt_pair(v10, v11);
            }
        }
}

// ---------------- flash attention (split-KV): partial O + (m,l) --------------
// grid (16 q-tiles, 2 kv-halves, B_), block 128 (4 warps x 16 q-rows). chunk 32.
__global__ void __launch_bounds__(128)
flash_attn(const uint2* __restrict__ Qhl, const uint2* __restrict__ Khl,
           const float* __restrict__ Vf,
           float* __restrict__ AV0, float* __restrict__ AV1,
           float* __restrict__ M0, float* __restrict__ L0,
           float* __restrict__ M1, float* __restrict__ L1)
{
    __shared__ __align__(16) uint2 Ks[32 * 68];   // [kv][dp] pitch 68
    __shared__ __align__(16) uint2 Vs[16 * 132];  // [kvp][d] pitch 132

    int b = blockIdx.z, half = blockIdx.y, m0t = blockIdx.x * 64;
    int kvOff = half * 512;
    int t = threadIdx.x, w = t >> 5, lane = t & 31;
    int g = lane >> 2, l3 = lane & 3;
    int r0 = m0t + w * 16 + g, r1 = r0 + 8;

    // ---- Q fragments (registers for whole kernel) ----
    uint32_t qhi[8][4], qlo[8][4];
    {
        const uint2* Q0 = Qhl + ((ll)b * LP_ + r0) * 64;
        const uint2* Q1 = Qhl + ((ll)b * LP_ + r1) * 64;
        #pragma unroll
        for (int s = 0; s < 8; s++) {
            uint2 u0 = make_uint2(0u,0u), u2 = u0, u1 = u0, u3 = u0;
            if (r0 < LP_) { u0 = Q0[8*s + l3]; u2 = Q0[8*s + l3 + 4]; }
            if (r1 < LP_) { u1 = Q1[8*s + l3]; u3 = Q1[8*s + l3 + 4]; }
            qhi[s][0] = u0.x; qlo[s][0] = u0.y;
            qhi[s][1] = u1.x; qlo[s][1] = u1.y;
            qhi[s][2] = u2.x; qlo[s][2] = u2.y;
            qhi[s][3] = u3.x; qlo[s][3] = u3.y;
        }
    }

    float accO[16][4] = {};
    float m0_ = -1e30f, m1_ = -1e30f, l0_ = 0.f, l1_ = 0.f;

    int kvp = t >> 3, dseg = (t & 7) * 16;   // V loader indices

    for (int iter = 0; iter < 16; iter++) {
        int kb = kvOff + iter * 32;
        // ---- prefetch K chunk (32 rows x 32 uint4; j=0..7) ----
        uint4 kreg[8];
        #pragma unroll
        for (int j = 0; j < 8; j++) {
            int idx = t + 128 * j, row = idx >> 5, q4 = idx & 31;
            int gkv = kb + row;
            kreg[j] = (gkv < LP_)
                ? *(const uint4*)(Khl + ((ll)b * LP_ + gkv) * 64 + q4 * 2)
                : make_uint4(0u,0u,0u,0u);
        }
        float4 fA[4], fB[4];
        {
            int rA = kb + 2 * kvp, rB = rA + 1;
            #pragma unroll
            for (int dd = 0; dd < 4; dd++) {
                fA[dd] = (rA < LP_) ? *(const float4*)(Vf + ((ll)b * LP_ + rA) * 128 + dseg + 4*dd)
                                    : make_float4(0.f,0.f,0.f,0.f);
                fB[dd] = (rB < LP_) ? *(const float4*)(Vf + ((ll)b * LP_ + rB) * 128 + dseg + 4*dd)
                                    : make_float4(0.f,0.f,0.f,0.f);
            }
        }
        __syncthreads();
        #pragma unroll
        for (int j = 0; j < 8; j++) {
            int idx = t + 128 * j, row = idx >> 5, q4 = idx & 31;
            *(uint4*)&Ks[row * 68 + q4 * 2] = kreg[j];
        }
        #pragma unroll
        for (int dd = 0; dd < 4; dd++) {
            uint2 p0 = cvt_pair(fA[dd].x, fB[dd].x);
            uint2 p1 = cvt_pair(fA[dd].y, fB[dd].y);
            uint2 p2 = cvt_pair(fA[dd].z, fB[dd].z);
            uint2 p3 = cvt_pair(fA[dd].w, fB[dd].w);
            uint2* vp = &Vs[kvp * 132 + dseg + 4*dd];
            *(uint4*)vp       = make_uint4(p0.x, p0.y, p1.x, p1.y);
            *(uint4*)(vp + 2) = make_uint4(p2.x, p2.y, p3.x, p3.y);
        }
        __syncthreads();

        // ---- S = Q @ K_chunk^T ----
        float sacc[4][4] = {};
        #pragma unroll
        for (int nt = 0; nt < 4; nt++) {
            int krow = nt * 8 + g;
            #pragma unroll
            for (int s = 0; s < 8; s++) {
                uint2 y0 = Ks[krow * 68 + 8*s + l3];
                uint2 y1 = Ks[krow * 68 + 8*s + l3 + 4];
                uint32_t bh[2] = {y0.x, y1.x}, bl[2] = {y0.y, y1.y};
                mma_bf16(sacc[nt], qhi[s], bh);
                mma_bf16(sacc[nt], qhi[s], bl);
                mma_bf16(sacc[nt], qlo[s], bh);
            }
        }

        // ---- online softmax ----
        float cm0 = -1e30f, cm1 = -1e30f;
        #pragma unroll
        for (int nt = 0; nt < 4; nt++) {
            cm0 = fmaxf(cm0, fmaxf(sacc[nt][0], sacc[nt][1]));
            cm1 = fmaxf(cm1, fmaxf(sacc[nt][2], sacc[nt][3]));
        }
        cm0 = fmaxf(cm0, __shfl_xor_sync(0xffffffffu, cm0, 1));
        cm0 = fmaxf(cm0, __shfl_xor_sync(0xffffffffu, cm0, 2));
        cm1 = fmaxf(cm1, __shfl_xor_sync(0xffffffffu, cm1, 1));
        cm1 = fmaxf(cm1, __shfl_xor_sync(0xffffffffu, cm1, 2));
        float mn0 = fmaxf(m0_, cm0), mn1 = fmaxf(m1_, cm1);
        float sc0 = __expf(m0_ - mn0), sc1 = __expf(m1_ - mn1);
        m0_ = mn0; m1_ = mn1;

        uint32_t phi[2][4], plo[2][4];
        float rs0 = 0.f, rs1 = 0.f;
        #pragma unroll
        for (int nt = 0; nt < 4; nt++) {
            int c0 = kb + nt * 8 + 2 * l3;
            bool v0 = c0 < LP_, v1 = (c0 + 1) < LP_;
            float p00 = v0 ? __expf(sacc[nt][0] - mn0) : 0.f;
            float p01 = v1 ? __expf(sacc[nt][1] - mn0) : 0.f;
            float p10 = v0 ? __expf(sacc[nt][2] - mn1) : 0.f;
            float p11 = v1 ? __expf(sacc[nt][3] - mn1) : 0.f;
            rs0 += p00 + p01; rs1 += p10 + p11;
            uint2 hA = cvt_pair(p00, p01);
            uint2 hB = cvt_pair(p10, p11);
            int s2 = nt >> 1, o = (nt & 1) * 2;
            phi[s2][o]     = hA.x; plo[s2][o]     = hA.y;
            phi[s2][o + 1] = hB.x; plo[s2][o + 1] = hB.y;
        }
        rs0 += __shfl_xor_sync(0xffffffffu, rs0, 1);
        rs0 += __shfl_xor_sync(0xffffffffu, rs0, 2);
        rs1 += __shfl_xor_sync(0xffffffffu, rs1, 1);
        rs1 += __shfl_xor_sync(0xffffffffu, rs1, 2);
        l0_ = l0_ * sc0 + rs0;
        l1_ = l1_ * sc1 + rs1;
        #pragma unroll
        for (int dt = 0; dt < 16; dt++) {
            accO[dt][0] *= sc0; accO[dt][1] *= sc0;
            accO[dt][2] *= sc1; accO[dt][3] *= sc1;
        }

        // ---- O += P @ V_chunk ----
        #pragma unroll
        for (int dt = 0; dt < 16; dt++) {
            #pragma unroll
            for (int s2 = 0; s2 < 2; s2++) {
                int vr = 8 * s2 + l3;
                uint2 y0 = Vs[vr * 132 + dt * 8 + g];
                uint2 y1 = Vs[(vr + 4) * 132 + dt * 8 + g];
                uint32_t bh[2] = {y0.x, y1.x}, bl[2] = {y0.y, y1.y};
                mma_bf16(accO[dt], phi[s2], bh);
                mma_bf16(accO[dt], phi[s2], bl);
                mma_bf16(accO[dt], plo[s2], bh);
            }
        }
    }

    // ---- write UNNORMALIZED partial O + (m,l) ----
    float* AVp = half ? AV1 : AV0;
    float* Mo  = half ? M1 : M0;
    float* Lo  = half ? L1 : L0;
    #pragma unroll
    for (int dt = 0; dt < 16; dt++) {
        int c = dt * 8 + 2 * l3;
        if (r0 < LP_)
            *(float2*)(AVp + ((ll)b * LP_ + r0) * 128 + c) =
                make_float2(accO[dt][0], accO[dt][1]);
        if (r1 < LP_)
            *(float2*)(AVp + ((ll)b * LP_ + r1) * 128 + c) =
                make_float2(accO[dt][2], accO[dt][3]);
    }
    if (l3 == 0) {
        if (r0 < LP_) { Mo[(ll)b * LP_ + r0] = m0_; Lo[(ll)b * LP_ + r0] = l0_; }
        if (r1 < LP_) { Mo[(ll)b * LP_ + r1] = m1_; Lo[(ll)b * LP_ + r1] = l1_; }
    }
}

// ---------------- prep_all: 5 weight repacks + bq + Wq0 GEMM -----------------
// grid dim3(32, 7): y=0..4 repack, y=5 bq, y=6 Wq0 = emb_w @ wq_w (x<5)
__global__ void __launch_bounds__(256)
prep_all(const float* wq_w, const float* wk_w, const float* wv_w,
         const float* wo_w, const float* jp_w, const float* jc_w,
         uint2* wkp, uint2* wvp, uint2* wop, uint2* jpp, uint2* jcp,
         const float* emb_b, const float* wq_b, float* bq,
         const float* emb_w, float* Wq0)
{
    __shared__ __align__(16) uint2 As[2 * 64 * 12];
    __shared__ __align__(16) uint2 Bs[2 * 8 * 132];
    int y = blockIdx.y;
    if (y == 6) {
        if (blockIdx.x >= 5) return;
        gemm_body<0, 1, false, 0, false>(emb_w, nullptr, nullptr, nullptr,
            nullptr, nullptr, nullptr, nullptr, wq_w,
            nullptr, Wq0, nullptr, E_, D_, D_, D_, D_, 1.f,
            blockIdx.x * 64, 0, As, Bs);
        return;
    }
    if (y == 5) {
        if (blockIdx.x == 0 && threadIdx.x < 128) {
            int n = threadIdx.x;
            float s = wq_b[n];
            for (int k = 0; k < D_; k++) s = fmaf(emb_b[k], wq_w[k * D_ + n], s);
            bq[n] = s;
        }
        return;
    }
    int i = blockIdx.x * 256 + threadIdx.x;
    const float* s; uint2* d;
    switch (y) {
        case 0: s = wk_w; d = wkp; break;
        case 1: s = wv_w; d = wvp; break;
        case 2: s = wo_w; d = wop; break;
        case 3: s = jp_w; d = jpp; break;
        default: s = jc_w; d = jcp; break;
    }
    int kp = i >> 7, n = i & 127;
    d[i] = cvt_pair(s[(2 * kp) * D_ + n], s[(2 * kp + 1) * D_ + n]);
}

__global__ void __launch_bounds__(256, 2)
gemm_qkv(const float* __restrict__ in_pe, const float* __restrict__ Wq0,
         const float* __restrict__ bq, uint2* __restrict__ Qhl,
         const float* __restrict__ in_pfx,
         const uint2* __restrict__ wkp, const float* __restrict__ wk_b,
         uint2* __restrict__ Khl,
         const uint2* __restrict__ wvp, const float* __restrict__ wv_b,
         float* __restrict__ Vf, float inv_sqrt_d)
{
    __shared__ __align__(16) uint2 As[2 * 64 * 12];
    __shared__ __align__(16) uint2 Bs[2 * 8 * 132];
    int m0 = blockIdx.y * 64;
    if (blockIdx.z == 0)
        gemm_body<0, 1, false, 1, false>(in_pe, nullptr, nullptr, nullptr,
            nullptr, nullptr, nullptr, nullptr, Wq0,
            bq, nullptr, Qhl, B_*LP_, D_, E_, E_, D_, inv_sqrt_d, m0, 0, As, Bs);
    else if (blockIdx.z == 1)
        gemm_body<0, 0, false, 1, false>(in_pfx, nullptr, nullptr, nullptr,
            nullptr, nullptr, nullptr, wkp, nullptr,
            wk_b, nullptr, Khl, B_*LP_, D_, D_, D_, D_, 1.f, m0, 0, As, Bs);
    else
        gemm_body<0, 0, false, 0, false>(in_pfx, nullptr, nullptr, nullptr,
            nullptr, nullptr, nullptr, wvp, nullptr,
            wv_b, Vf, nullptr, B_*LP_, D_, D_, D_, D_, 1.f, m0, 0, As, Bs);
}

// pf = combine(AV0,AV1;m,l) @ wo + b   (flash combine fused into A-loader)
__global__ void __launch_bounds__(256, 2)
gemm_wo(const float* __restrict__ AV0, const float* __restrict__ AV1,
        const float* __restrict__ M0, const float* __restrict__ L0,
        const float* __restrict__ M1, const float* __restrict__ L1,
        const uint2* __restrict__ wop, const float* __restrict__ wo_b,
        float* __restrict__ pf)
{
    __shared__ __align__(16) uint2 As[2 * 64 * 12];
    __shared__ __align__(16) uint2 Bs[2 * 8 * 132];
    gemm_body<4, 0, false, 0, false>(AV0, AV1, M0, L0, M1, L1,
        nullptr, wop, nullptr,
        wo_b, pf, nullptr, B_*LP_, D_, D_, D_, D_, 1.f, blockIdx.y * 64, 0, As, Bs);
}

__global__ void __launch_bounds__(256, 2)
gemm_pc(const float* __restrict__ pf, const uint2* __restrict__ jpp,
        const float* __restrict__ jp_b, float* __restrict__ P,
        const float* __restrict__ cf, const uint2* __restrict__ jcp,
        const float* __restrict__ jc_b, uint2* __restrict__ Chl)
{
    if (blockIdx.z == 1 && blockIdx.y >= 8) return;
    __shared__ __align__(16) uint2 As[2 * 64 * 12];
    __shared__ __align__(16) uint2 Bs[2 * 8 * 132];
    int m0 = blockIdx.y * 64;
    if (blockIdx.z == 0)
        gemm_body<1, 0, false, 0, false>(pf, nullptr, nullptr, nullptr,
            nullptr, nullptr, nullptr, jpp, nullptr,
            jp_b, P, nullptr, B_*LP_, D_, D_, D_, D_, 1.f, m0, 0, As, Bs);
    else
        gemm_body<1, 0, false, 1, false>(cf, nullptr, nullptr, nullptr,
            nullptr, nullptr, nullptr, jcp, nullptr,
            jc_b, nullptr, Chl, B_*NC_, D_, D_, D_, D_, 1.f, m0, 0, As, Bs);
}

// ---------------- A-logits: bf16x3 64x64 GEMM + sigmoid + partial sums -------
__global__ void __launch_bounds__(256, 2)
alogits_kernel(const float* __restrict__ Pm, const uint2* __restrict__ Chl,
               float* __restrict__ Aout, float* __restrict__ Apart)
{
    __shared__ __align__(16) uint2 As[2][768];
    __shared__ __align__(16) uint2 Bs[2][768];
    __shared__ float red[256];

    int b = blockIdx.y, mt = blockIdx.x, m0 = mt * 64;
    const float* A = Pm + (ll)b * LP_ * D_;
    const uint2* Bh = Chl + (ll)b * NC_ * 64;
    float* C = Aout + (ll)b * LP_ * NC_;
    int t = threadIdx.x, warp = t >> 5, lane = t & 31;
    int g = lane >> 2, l3 = lane & 3;
    int wm = (warp & 1) * 32, wn = (warp >> 1) * 16;

    float acc[2][2][4] = {};
    int ar = t >> 2, akf = (t & 3) * 4, akp = (t & 3) * 2;
    uint4 ua, ub;

    auto loadAB = [&](int k0) {
        int gm = m0 + ar;
        float4 rv = make_float4(0.f, 0.f, 0.f, 0.f);
        if (gm < LP_) rv = *(const float4*)(A + (ll)gm * D_ + k0 + akf);
        uint2 p0 = cvt_pair(rv.x, rv.y), p1 = cvt_pair(rv.z, rv.w);
        ua = make_uint4(p0.x, p0.y, p1.x, p1.y);
        ub = *(const uint4*)(Bh + (ll)ar * 64 + (k0 >> 1) + akp);
    };
    auto storeAB = [&](int s) {
        *(uint4*)&As[s][ar * 12 + akp] = ua;
        *(uint4*)&Bs[s][ar * 12 + akp] = ub;
    };
    loadAB(0); storeAB(0);
    __syncthreads();

    for (int it = 0; it < 8; it++) {
        int s = it & 1;
        if (it < 7) loadAB((it + 1) << 4);
        uint32_t ahi[2][4], alo[2][4];
        #pragma unroll
        for (int mi = 0; mi < 2; mi++) {
            int rr = wm + mi * 16 + g;
            uint2 x0 = As[s][rr * 12 + l3];
            uint2 x1 = As[s][(rr + 8) * 12 + l3];
            uint2 x2 = As[s][rr * 12 + l3 + 4];
            uint2 x3 = As[s][(rr + 8) * 12 + l3 + 4];
            ahi[mi][0] = x0.x; alo[mi][0] = x0.y;
            ahi[mi][1] = x1.x; alo[mi][1] = x1.y;
            ahi[mi][2] = x2.x; alo[mi][2] = x2.y;
            ahi[mi][3] = x3.x; alo[mi][3] = x3.y;
        }
        uint32_t bhi[2][2], blo[2][2];
        #pragma unroll
        for (int ni = 0; ni < 2; ni++) {
            int cc = wn + ni * 8 + g;
            uint2 y0 = Bs[s][cc * 12 + l3];
            uint2 y1 = Bs[s][cc * 12 + l3 + 4];
            bhi[ni][0] = y0.x; blo[ni][0] = y0.y;
            bhi[ni][1] = y1.x; blo[ni][1] = y1.y;
        }
        #pragma unroll
        for (int mi = 0; mi < 2; mi++)
            #pragma unroll
            for (int ni = 0; ni < 2; ni++) {
                mma_bf16(acc[mi][ni], ahi[mi], bhi[ni]);
                mma_bf16(acc[mi][ni], ahi[mi], blo[ni]);
                mma_bf16(acc[mi][ni], alo[mi], bhi[ni]);
            }
        if (it < 7) storeAB(s ^ 1);
        __syncthreads();
    }

    float tsum = 0.f;
    #pragma unroll
    for (int mi = 0; mi < 2; mi++)
        #pragma unroll
        for (int ni = 0; ni < 2; ni++) {
            int r0 = m0 + wm + mi * 16 + g;
            int c0 = wn + ni * 8 + 2 * l3;
            if (r0 < LP_) {
                float v0 = 1.f / (1.f + __expf(-acc[mi][ni][0]));
                float v1 = 1.f / (1.f + __expf(-acc[mi][ni][1]));
                *(float2*)(C + (ll)r0 * NC_ + c0) = make_float2(v0, v1);
                tsum += v0 + v1;
            }
            if (r0 + 8 < LP_) {
                float v0 = 1.f / (1.f + __expf(-acc[mi][ni][2]));
                float v1 = 1.f / (1.f + __expf(-acc[mi][ni][3]));
                *(float2*)(C + (ll)(r0 + 8) * NC_ + c0) = make_float2(v0, v1);
                tsum += v0 + v1;
            }
        }
    red[t] = tsum; __syncthreads();
    for (int s2 = 128; s2 > 0; s2 >>= 1) {
        if (t < s2) red[t] += red[t + s2];
        __syncthreads();
    }
    if (t == 0) Apart[b * 16 + mt] = red[0];
}

// ---------------- tanh outer-product weighted reduction ---------------------
__global__ void tanh_outer_kernel(const float* __restrict__ pf,
                                  const float* __restrict__ cf,
                                  const float* __restrict__ A,
                                  float* __restrict__ part)
{
    int b = blockIdx.y, tile = blockIdx.x;
    int d = threadIdx.x;  // 128
    __shared__ float cfs[NC_ * D_];
    for (int i = threadIdx.x; i < NC_ * D_; i += 128)
        cfs[i] = cf[(ll)b * NC_ * D_ + i];
    __syncthreads();
    float acc = 0.f;
    int i0 = tile * ITILE_;
    for (int i = i0; i < i0 + ITILE_; i++) {
        float pv = pf[((ll)b * LP_ + i) * D_ + d];
        const float* Ar = A + ((ll)b * LP_ + i) * NC_;
        #pragma unroll 4
        for (int k = 0; k < NC_; k++) {
            float w = Ar[k];
            float x = pv * cfs[k * D_ + d];
            float th;
            asm("tanh.approx.f32 %0, %1;" : "=f"(th) : "f"(x));
            acc = fmaf(th, w, acc);
        }
    }
    part[((ll)b * NTILE_ + tile) * D_ + d] = acc;
}

__global__ void cp_reduce_kernel(const float* __restrict__ part,
                                 const float* __restrict__ Apart,
                                 float* __restrict__ cp)
{
    int b = blockIdx.x;
    int d = threadIdx.x;  // 128
    float as = 0.f;
    #pragma unroll
    for (int j = 0; j < 16; j++) as += Apart[b * 16 + j];
    float s = 0.f;
    for (int t2 = 0; t2 < NTILE_; t2++)
        s += part[((ll)b * NTILE_ + t2) * D_ + d];
    cp[b * D_ + d] = s / as;
}

// ---------------- skinny GEMM (M = 8 rows) -----------------------------------
template<bool RELU_OUT>
__global__ void __launch_bounds__(256)
skinny_gemm(const float* __restrict__ A, const float* __restrict__ W,
            const float* __restrict__ bias, float* __restrict__ C,
            int N, int K)
{
    __shared__ float As[8 * 1024];
    __shared__ float red[8][8][32];
    int t = threadIdx.x;
    for (int i = t; i < 8 * K; i += 256) As[i] = A[i];
    __syncthreads();
    int n = blockIdx.x * 32 + (t & 31);
    int ks = t >> 5;
    int kseg = K >> 3;
    float acc[8] = {};
    if (n < N) {
        for (int k = ks * kseg; k < (ks + 1) * kseg; k++) {
            float w = W[(ll)k * N + n];
            #pragma unroll
            for (int m = 0; m < 8; m++) acc[m] = fmaf(As[m * K + k], w, acc[m]);
        }
    }
    #pragma unroll
    for (int m = 0; m < 8; m++) red[ks][m][t & 31] = acc[m];
    __syncthreads();
    int m = t >> 5, lnn = t & 31;
    int nn = blockIdx.x * 32 + lnn;
    if (nn < N) {
        float s = 0.f;
        #pragma unroll
        for (int j = 0; j < 8; j++) s += red[j][m][lnn];
        s += bias[nn];
        if (RELU_OUT) s = fmaxf(s, 0.f);
        C[(ll)m * N + nn] = s;
    }
}

// ---------------- launch ------------------------------------------------------
extern "C" void kernel_launch(void* const* d_in, const int* in_sizes, int n_in,
                              void* d_out, int out_size)
{
    const float* in_pe  = (const float*)d_in[0];
    const float* in_pfx = (const float*)d_in[1];
    const float* in_cf  = (const float*)d_in[2];
    const float* emb_w = (const float*)d_in[3];  const float* emb_b = (const float*)d_in[4];
    const float* wq_w  = (const float*)d_in[5];  const float* wq_b  = (const float*)d_in[6];
    const float* wk_w  = (const float*)d_in[7];  const float* wk_b  = (const float*)d_in[8];
    const float* wv_w  = (const float*)d_in[9];  const float* wv_b  = (const float*)d_in[10];
    const float* wo_w  = (const float*)d_in[11]; const float* wo_b  = (const float*)d_in[12];
    const float* jp_w  = (const float*)d_in[13]; const float* jp_b  = (const float*)d_in[14];
    const float* jc_w  = (const float*)d_in[15]; const float* jc_b  = (const float*)d_in[16];
    const float* c1_w  = (const float*)d_in[17]; const float* c1_b  = (const float*)d_in[18];
    const float* c2_w  = (const float*)d_in[19]; const float* c2_b  = (const float*)d_in[20];
    const float* c3_w  = (const float*)d_in[21]; const float* c3_b  = (const float*)d_in[22];
    const float* c4_w  = (const float*)d_in[23]; const float* c4_b  = (const float*)d_in[24];

    uint2 *Qhl, *Khl, *Chl, *wkp, *wvp, *wop, *jpp, *jcp;
    float *Wq0, *Vf, *AV0, *AV1, *M0, *L0, *M1, *L1, *pf, *P, *A, *bq, *Apart,
          *part, *cp, *h1, *h2, *h3;
    cudaGetSymbolAddress((void**)&Qhl,  g_Qhl);
    cudaGetSymbolAddress((void**)&Khl,  g_Khl);
    cudaGetSymbolAddress((void**)&Chl,  g_Chl);
    cudaGetSymbolAddress((void**)&wkp,  g_wkp);
    cudaGetSymbolAddress((void**)&wvp,  g_wvp);
    cudaGetSymbolAddress((void**)&wop,  g_wop);
    cudaGetSymbolAddress((void**)&jpp,  g_jpp);
    cudaGetSymbolAddress((void**)&jcp,  g_jcp);
    cudaGetSymbolAddress((void**)&Wq0,  g_Wq0);
    cudaGetSymbolAddress((void**)&Vf,   g_Vf);
    cudaGetSymbolAddress((void**)&AV0,  g_AV0);
    cudaGetSymbolAddress((void**)&AV1,  g_AV1);
    cudaGetSymbolAddress((void**)&M0,   g_M0);
    cudaGetSymbolAddress((void**)&L0,   g_L0);
    cudaGetSymbolAddress((void**)&M1,   g_M1);
    cudaGetSymbolAddress((void**)&L1,   g_L1);
    cudaGetSymbolAddress((void**)&pf,   g_pf);
    cudaGetSymbolAddress((void**)&P,    g_P);
    cudaGetSymbolAddress((void**)&A,    g_A);
    cudaGetSymbolAddress((void**)&bq,   g_bq);
    cudaGetSymbolAddress((void**)&Apart,g_Apart);
    cudaGetSymbolAddress((void**)&part, g_part);
    cudaGetSymbolAddress((void**)&cp,   g_cp);
    cudaGetSymbolAddress((void**)&h1,   g_h1);
    cudaGetSymbolAddress((void**)&h2,   g_h2);
    cudaGetSymbolAddress((void**)&h3,   g_h3);

    const float inv_sqrt_d = 0.088388347648318440550f;  // 1/sqrt(128)

    // 0. one prep launch: 5 weight repacks + bq + Wq0 = emb_w @ wq_w
    prep_all<<<dim3(32,7),256>>>(wq_w, wk_w, wv_w, wo_w, jp_w, jc_w,
                                 wkp, wvp, wop, jpp, jcp,
                                 emb_b, wq_b, bq, emb_w, Wq0);
    // 1. Q/K/V (Q: B packed on the fly from Wq0 fp32)
    gemm_qkv<<<dim3(1,125,3),256>>>(in_pe, Wq0, bq, Qhl,
                                    in_pfx, wkp, wk_b, Khl,
                                    wvp, wv_b, Vf, inv_sqrt_d);
    // 2. split-KV flash attention -> partial O + (m,l)
    flash_attn<<<dim3(16,2,B_),128>>>(Qhl, Khl, Vf, AV0, AV1, M0, L0, M1, L1);
    // 3. pf = combine(AV partials) @ wo + b   (combine fused in A-loader)
    gemm_wo<<<dim3(1,125),256>>>(AV0, AV1, M0, L0, M1, L1, wop, wo_b, pf);
    // 4. P / Chl
    gemm_pc<<<dim3(1,125,2),256>>>(pf, jpp, jp_b, P, in_cf, jcp, jc_b, Chl);
    // 5. A = sigmoid(P @ C^T) + partial sums
    alogits_kernel<<<dim3(16,B_),256>>>(P, Chl, A, Apart);
    // 6. tanh outer product partials
    tanh_outer_kernel<<<dim3(NTILE_,B_),128>>>(pf, in_cf, A, part);
    // 7. reduce + normalize
    cp_reduce_kernel<<<B_,128>>>(part, Apart, cp);
    // 8-11. classifier MLP
    skinny_gemm<true ><<<32,256>>>(cp, c1_w, c1_b, h1, 1024, D_);
    skinny_gemm<true ><<<32,256>>>(h1, c2_w, c2_b, h2, 1024, 1024);
    skinny_gemm<true ><<<8, 256>>>(h2, c3_w, c3_b, h3, 256, 1024);
    skinny_gemm<false><<<1, 256>>>(h3, c4_w, c4_b, (float*)d_out, 1, 256);
}